// round 3
// baseline (speedup 1.0000x reference)
#include <cuda_runtime.h>

#define B_ 2
#define S_ 2048
#define D_ 768
#define H_ 12
#define DK_ 64
#define R_ 8
#define N_ 4096   // B_*S_

// ---------------- scratch (static device globals; no allocation) ----------------
__device__ float g_Aq[N_ * R_];
__device__ float g_Av[N_ * R_];
__device__ float g_Qadj[(size_t)N_ * D_];
__device__ float g_Vadj[(size_t)N_ * D_];
__device__ float g_qh[(size_t)N_ * D_];   // [B,H,S,DK], pre-scaled by 1/8
__device__ float g_kh[(size_t)N_ * D_];   // [B,H,S,DK]
__device__ float g_vh[(size_t)N_ * D_];   // [B,H,S,DK]
__device__ float g_ao[(size_t)N_ * D_];   // [B,S,D] attention output
__device__ unsigned g_mw[B_ * S_ * (S_ / 32)];  // packed mask bits

// ---------------- tf32 / cp.async helpers ---------------------------------------
__device__ __forceinline__ unsigned f2tf(float f) {
    unsigned u;
    asm("cvt.rna.tf32.f32 %0, %1;" : "=r"(u) : "f"(f));
    return u;
}
__device__ __forceinline__ uint4 cvt4(float4 v) {
    return make_uint4(f2tf(v.x), f2tf(v.y), f2tf(v.z), f2tf(v.w));
}
__device__ __forceinline__ void mma8(float* c, const unsigned* a, const unsigned* b) {
    asm volatile(
        "mma.sync.aligned.m16n8k8.row.col.f32.tf32.tf32.f32 "
        "{%0,%1,%2,%3}, {%4,%5,%6,%7}, {%8,%9}, {%0,%1,%2,%3};"
        : "+f"(c[0]), "+f"(c[1]), "+f"(c[2]), "+f"(c[3])
        : "r"(a[0]), "r"(a[1]), "r"(a[2]), "r"(a[3]), "r"(b[0]), "r"(b[1]));
}
__device__ __forceinline__ void cp16(unsigned dst, const void* src) {
    asm volatile("cp.async.cg.shared.global [%0], [%1], 16;" :: "r"(dst), "l"(src));
}
__device__ __forceinline__ void cp_commit() {
    asm volatile("cp.async.commit_group;");
}
template <int NN>
__device__ __forceinline__ void cp_wait() {
    asm volatile("cp.async.wait_group %0;" :: "n"(NN));
}

// ---------------- K0: x[N,768] @ A[768,8] -> out[N,8]  (one warp per row) ------
__global__ void lora_down_kernel(const float* __restrict__ x,
                                 const float* __restrict__ A,
                                 float* __restrict__ out) {
    int warp = (blockIdx.x * blockDim.x + threadIdx.x) >> 5;
    int lane = threadIdx.x & 31;
    if (warp >= N_) return;
    float acc[8] = {0.f,0.f,0.f,0.f,0.f,0.f,0.f,0.f};
    const float* xr = x + (size_t)warp * D_;
    for (int k = lane; k < D_; k += 32) {
        float xv = xr[k];
        float4 a0 = *(const float4*)(A + k * 8);
        float4 a1 = *(const float4*)(A + k * 8 + 4);
        acc[0] += xv * a0.x; acc[1] += xv * a0.y; acc[2] += xv * a0.z; acc[3] += xv * a0.w;
        acc[4] += xv * a1.x; acc[5] += xv * a1.y; acc[6] += xv * a1.z; acc[7] += xv * a1.w;
    }
    #pragma unroll
    for (int r = 0; r < 8; r++) {
        #pragma unroll
        for (int off = 16; off > 0; off >>= 1)
            acc[r] += __shfl_xor_sync(0xffffffffu, acc[r], off);
    }
    if (lane == 0) {
        float4* o = (float4*)(out + (size_t)warp * 8);
        o[0] = make_float4(acc[0], acc[1], acc[2], acc[3]);
        o[1] = make_float4(acc[4], acc[5], acc[6], acc[7]);
    }
}

// -------- K1: out = x + Ar[N,8] @ Bm[8,768]  ------------------------------------
__global__ void lora_up_kernel(const float* __restrict__ x,
                               const float* __restrict__ Ar,
                               const float* __restrict__ Bm,
                               float* __restrict__ out) {
    int i = blockIdx.x * blockDim.x + threadIdx.x;
    int row = i / D_;
    int col = i - row * D_;
    float4 a0 = *(const float4*)(Ar + (size_t)row * 8);
    float4 a1 = *(const float4*)(Ar + (size_t)row * 8 + 4);
    float s = x[i];
    s += a0.x * Bm[0 * D_ + col];
    s += a0.y * Bm[1 * D_ + col];
    s += a0.z * Bm[2 * D_ + col];
    s += a0.w * Bm[3 * D_ + col];
    s += a1.x * Bm[4 * D_ + col];
    s += a1.y * Bm[5 * D_ + col];
    s += a1.z * Bm[6 * D_ + col];
    s += a1.w * Bm[7 * D_ + col];
    out[i] = s;
}

// -------- K1b: pack mask ints into bits -----------------------------------------
__global__ void mask_pack_kernel(const int* __restrict__ mask,
                                 unsigned* __restrict__ mw) {
    int w = blockIdx.x * blockDim.x + threadIdx.x;
    const int4* mp = (const int4*)(mask + (size_t)w * 32);
    unsigned bits = 0;
    #pragma unroll
    for (int j = 0; j < 8; j++) {
        int4 v = mp[j];
        bits |= (v.x != 0 ? 1u : 0u) << (j * 4 + 0);
        bits |= (v.y != 0 ? 1u : 0u) << (j * 4 + 1);
        bits |= (v.z != 0 ? 1u : 0u) << (j * 4 + 2);
        bits |= (v.w != 0 ? 1u : 0u) << (j * 4 + 3);
    }
    mw[w] = bits;
}

// ---- K2: tf32 GEMM  C = scale*(A @ W^T + bias), cp.async double-buffered -------
// 256 threads = 8 warps (4m x 2n), BM=128, BN=64, BK=32, warp tile 32x32.
#define GST 36
#define GEMM_SMEM ((2 * 128 * GST + 2 * 64 * GST) * 4)
__global__ void __launch_bounds__(256)
gemm_tf32_kernel(const float* __restrict__ A, const float* __restrict__ W,
                 const float* __restrict__ bias, float* __restrict__ C,
                 float scale, int headPermute) {
    extern __shared__ float gsm[];
    float* As = gsm;                      // [2][128][GST] fp32
    float* Bs = gsm + 2 * 128 * GST;      // [2][64][GST]  fp32
    int tid = threadIdx.x;
    int warp = tid >> 5, lane = tid & 31;
    int wm = warp >> 1, wn = warp & 1;
    int lr = lane >> 2, lc = lane & 3;
    int i0 = blockIdx.x * 128, n0 = blockIdx.y * 64;

    unsigned sA = (unsigned)__cvta_generic_to_shared(As);
    unsigned sB = (unsigned)__cvta_generic_to_shared(Bs);

    float c[2][4][4];
    #pragma unroll
    for (int mi = 0; mi < 2; mi++)
        #pragma unroll
        for (int ni = 0; ni < 4; ni++)
            #pragma unroll
            for (int q = 0; q < 4; q++) c[mi][ni][q] = 0.f;

    int lrow = tid >> 3, lc4 = (tid & 7) << 2;

    // issue tile 0
    {
        #pragma unroll
        for (int p = 0; p < 4; p++) {
            int row = lrow + p * 32;
            cp16(sA + (unsigned)(row * GST + lc4) * 4,
                 A + (size_t)(i0 + row) * D_ + lc4);
        }
        #pragma unroll
        for (int p = 0; p < 2; p++) {
            int row = lrow + p * 32;
            cp16(sB + (unsigned)(row * GST + lc4) * 4,
                 W + (size_t)(n0 + row) * D_ + lc4);
        }
        cp_commit();
    }

    for (int it = 0; it < 24; it++) {
        int buf = it & 1;
        if (it + 1 < 24) {
            int nb = (it + 1) & 1;
            int k0 = (it + 1) * 32;
            #pragma unroll
            for (int p = 0; p < 4; p++) {
                int row = lrow + p * 32;
                cp16(sA + (unsigned)((nb * 128 + row) * GST + lc4) * 4,
                     A + (size_t)(i0 + row) * D_ + k0 + lc4);
            }
            #pragma unroll
            for (int p = 0; p < 2; p++) {
                int row = lrow + p * 32;
                cp16(sB + (unsigned)((nb * 64 + row) * GST + lc4) * 4,
                     W + (size_t)(n0 + row) * D_ + k0 + lc4);
            }
            cp_commit();
            cp_wait<1>();
        } else {
            cp_wait<0>();
        }
        __syncthreads();

        const float* Ab = As + buf * 128 * GST;
        const float* Bb = Bs + buf * 64 * GST;
        #pragma unroll
        for (int kk = 0; kk < 32; kk += 8) {
            unsigned a[2][4], bf[4][2];
            #pragma unroll
            for (int mi = 0; mi < 2; mi++) {
                int r = wm * 32 + mi * 16 + lr;
                a[mi][0] = f2tf(Ab[r * GST + kk + lc]);
                a[mi][1] = f2tf(Ab[(r + 8) * GST + kk + lc]);
                a[mi][2] = f2tf(Ab[r * GST + kk + lc + 4]);
                a[mi][3] = f2tf(Ab[(r + 8) * GST + kk + lc + 4]);
            }
            #pragma unroll
            for (int ni = 0; ni < 4; ni++) {
                int n = wn * 32 + ni * 8 + lr;
                bf[ni][0] = f2tf(Bb[n * GST + kk + lc]);
                bf[ni][1] = f2tf(Bb[n * GST + kk + lc + 4]);
            }
            #pragma unroll
            for (int mi = 0; mi < 2; mi++)
                #pragma unroll
                for (int ni = 0; ni < 4; ni++)
                    mma8(c[mi][ni], a[mi], bf[ni]);
        }
        __syncthreads();
    }

    #pragma unroll
    for (int mi = 0; mi < 2; mi++) {
        #pragma unroll
        for (int ni = 0; ni < 4; ni++) {
            int i = i0 + wm * 32 + mi * 16 + lr;
            int j = n0 + wn * 32 + ni * 8 + 2 * lc;
            float b0 = bias[j], b1 = bias[j + 1];
            float2 o0 = make_float2(scale * (c[mi][ni][0] + b0), scale * (c[mi][ni][1] + b1));
            float2 o1 = make_float2(scale * (c[mi][ni][2] + b0), scale * (c[mi][ni][3] + b1));
            if (headPermute) {
                int bb = i >> 11, s = i & 2047;
                int hh = j >> 6, dk = j & 63;
                *(float2*)(C + (((size_t)(bb * H_ + hh)) * S_ + s) * DK_ + dk) = o0;
                *(float2*)(C + (((size_t)(bb * H_ + hh)) * S_ + (s + 8)) * DK_ + dk) = o1;
            } else {
                *(float2*)(C + (size_t)i * D_ + j) = o0;
                *(float2*)(C + (size_t)(i + 8) * D_ + j) = o1;
            }
        }
    }
}

// ---------------- K3: flash attention, tf32 mma, cp.async double-buffered -------
// 256 threads = 8 warps, warp strip 16 q-rows, BM=128, KV tile 64.
#define AST 68
#define ATTN_SMEM ((128 * AST + 2 * 64 * AST + 2 * 64 * AST + 128 * AST) * 4)
__global__ void __launch_bounds__(256)
attn_tc_kernel(const unsigned* __restrict__ mw, float* __restrict__ out) {
    extern __shared__ unsigned sm[];
    unsigned* Qs = sm;                       // [128][AST] tf32
    float*    Kb = (float*)(Qs + 128 * AST); // [2][64][AST] fp32
    float*    Vb = Kb + 2 * 64 * AST;        // [2][64][AST] fp32
    unsigned* Ps = (unsigned*)(Vb + 2 * 64 * AST); // [128][AST] tf32

    int tid = threadIdx.x, warp = tid >> 5, lane = tid & 31;
    int lr = lane >> 2, lc = lane & 3;
    int rb = warp * 16;
    int qb = blockIdx.x, h = blockIdx.y, b = blockIdx.z;
    int q0 = qb * 128, bh = b * H_ + h;

    const float* qg = g_qh + ((size_t)bh * S_ + q0) * DK_;
    const float* kg = g_kh + (size_t)bh * S_ * DK_;
    const float* vg = g_vh + (size_t)bh * S_ * DK_;

    unsigned sK = (unsigned)__cvta_generic_to_shared(Kb);
    unsigned sV = (unsigned)__cvta_generic_to_shared(Vb);

    int lrow = tid >> 4, lc4 = (tid & 15) << 2;   // 64-col rows: 16 float4/row

    // Q -> smem (tf32), 128 rows
    #pragma unroll
    for (int p = 0; p < 8; p++) {
        int row = lrow + p * 16;
        *(uint4*)&Qs[row * AST + lc4] = cvt4(*(const float4*)(qg + (size_t)row * DK_ + lc4));
    }

    // issue KV tile 0
    #pragma unroll
    for (int p = 0; p < 4; p++) {
        int row = lrow + p * 16;
        cp16(sK + (unsigned)(row * AST + lc4) * 4, kg + (size_t)row * DK_ + lc4);
        cp16(sV + (unsigned)(row * AST + lc4) * 4, vg + (size_t)row * DK_ + lc4);
    }
    cp_commit();

    float o[8][4];
    float m[2], l[2];
    m[0] = -1e30f; m[1] = -1e30f; l[0] = 0.f; l[1] = 0.f;
    #pragma unroll
    for (int ni = 0; ni < 8; ni++)
        #pragma unroll
        for (int q = 0; q < 4; q++) o[ni][q] = 0.f;

    for (int kb = 0; kb < S_ / 64; kb++) {
        int buf = kb & 1;
        if (kb + 1 < S_ / 64) {
            int nb = (kb + 1) & 1;
            int k0n = (kb + 1) * 64;
            #pragma unroll
            for (int p = 0; p < 4; p++) {
                int row = lrow + p * 16;
                cp16(sK + (unsigned)((nb * 64 + row) * AST + lc4) * 4,
                     kg + (size_t)(k0n + row) * DK_ + lc4);
                cp16(sV + (unsigned)((nb * 64 + row) * AST + lc4) * 4,
                     vg + (size_t)(k0n + row) * DK_ + lc4);
            }
            cp_commit();
            cp_wait<1>();
        } else {
            cp_wait<0>();
        }
        __syncthreads();

        const float* Ks = Kb + buf * 64 * AST;
        const float* Vs = Vb + buf * 64 * AST;

        // --- S = Q K^T (q pre-scaled by 1/8) ---
        float s[8][4];
        #pragma unroll
        for (int ni = 0; ni < 8; ni++)
            #pragma unroll
            for (int q = 0; q < 4; q++) s[ni][q] = 0.f;

        #pragma unroll
        for (int kk = 0; kk < 64; kk += 8) {
            unsigned a[4], bf[8][2];
            a[0] = Qs[(rb + lr) * AST + kk + lc];
            a[1] = Qs[(rb + 8 + lr) * AST + kk + lc];
            a[2] = Qs[(rb + lr) * AST + kk + lc + 4];
            a[3] = Qs[(rb + 8 + lr) * AST + kk + lc + 4];
            #pragma unroll
            for (int ni = 0; ni < 8; ni++) {
                int n = ni * 8 + lr;
                bf[ni][0] = f2tf(Ks[n * AST + kk + lc]);
                bf[ni][1] = f2tf(Ks[n * AST + kk + lc + 4]);
            }
            #pragma unroll
            for (int ni = 0; ni < 8; ni++)
                mma8(s[ni], a, bf[ni]);
        }

        // --- mask + online softmax + write P (tf32) to smem ---
        #pragma unroll
        for (int hh = 0; hh < 2; hh++) {
            int rloc = rb + hh * 8 + lr;
            int grow = q0 + rloc;
            uint2 w = *(const uint2*)(mw + ((size_t)b * S_ + grow) * (S_ / 32) + kb * 2);
            float rmax = -1e30f;
            #pragma unroll
            for (int ni = 0; ni < 8; ni++) {
                int col = ni * 8 + 2 * lc;
                unsigned ws = (col < 32) ? w.x : w.y;
                int bit = col & 31;
                float* sp = &s[ni][hh * 2];
                if (!((ws >> bit) & 1u))       sp[0] = -1e9f;
                if (!((ws >> (bit + 1)) & 1u)) sp[1] = -1e9f;
                rmax = fmaxf(rmax, fmaxf(sp[0], sp[1]));
            }
            rmax = fmaxf(rmax, __shfl_xor_sync(0xffffffffu, rmax, 1));
            rmax = fmaxf(rmax, __shfl_xor_sync(0xffffffffu, rmax, 2));
            float mn = fmaxf(m[hh], rmax);
            float corr = __expf(m[hh] - mn);
            m[hh] = mn;
            float rs = 0.f;
            #pragma unroll
            for (int ni = 0; ni < 8; ni++) {
                float* sp = &s[ni][hh * 2];
                float p0 = __expf(sp[0] - mn);
                float p1 = __expf(sp[1] - mn);
                rs += p0 + p1;
                int col = ni * 8 + 2 * lc;
                *(uint2*)&Ps[rloc * AST + col] = make_uint2(f2tf(p0), f2tf(p1));
                o[ni][hh * 2]     *= corr;
                o[ni][hh * 2 + 1] *= corr;
            }
            rs += __shfl_xor_sync(0xffffffffu, rs, 1);
            rs += __shfl_xor_sync(0xffffffffu, rs, 2);
            l[hh] = l[hh] * corr + rs;
        }
        __syncwarp();   // Ps rows are warp-private; order STS before LDS in-warp

        // --- O += P @ V ---
        #pragma unroll
        for (int kk = 0; kk < 64; kk += 8) {
            unsigned a[4], bf[8][2];
            a[0] = Ps[(rb + lr) * AST + kk + lc];
            a[1] = Ps[(rb + 8 + lr) * AST + kk + lc];
            a[2] = Ps[(rb + lr) * AST + kk + lc + 4];
            a[3] = Ps[(rb + 8 + lr) * AST + kk + lc + 4];
            #pragma unroll
            for (int ni = 0; ni < 8; ni++) {
                int n = ni * 8 + lr;
                bf[ni][0] = f2tf(Vs[(kk + lc) * AST + n]);
                bf[ni][1] = f2tf(Vs[(kk + lc + 4) * AST + n]);
            }
            #pragma unroll
            for (int ni = 0; ni < 8; ni++)
                mma8(o[ni], a, bf[ni]);
        }
        __syncthreads();   // all warps done with this buffer before next issue
    }

    // --- epilogue: O / l -> out [B,S,D] ---
    #pragma unroll
    for (int hh = 0; hh < 2; hh++) {
        float inv = 1.0f / l[hh];
        int grow = q0 + rb + hh * 8 + lr;
        #pragma unroll
        for (int ni = 0; ni < 8; ni++) {
            int col = ni * 8 + 2 * lc;
            float2 ov = make_float2(o[ni][hh * 2] * inv, o[ni][hh * 2 + 1] * inv);
            *(float2*)(out + ((size_t)(b * S_ + grow)) * D_ + h * DK_ + col) = ov;
        }
    }
}

// --------------------------------- host ----------------------------------------
extern "C" void kernel_launch(void* const* d_in, const int* in_sizes, int n_in,
                              void* d_out, int out_size) {
    const float* query = (const float*)d_in[0];
    const float* key   = (const float*)d_in[1];
    const float* value = (const float*)d_in[2];
    const int*   mask  = (const int*)d_in[3];
    const float* lAq   = (const float*)d_in[4];
    const float* lBq   = (const float*)d_in[5];
    const float* lAv   = (const float*)d_in[6];
    const float* lBv   = (const float*)d_in[7];
    const float* Wq    = (const float*)d_in[8];
    const float* bq    = (const float*)d_in[9];
    const float* Wk    = (const float*)d_in[10];
    const float* bk    = (const float*)d_in[11];
    const float* Wv    = (const float*)d_in[12];
    const float* bv    = (const float*)d_in[13];
    const float* Wm    = (const float*)d_in[14];
    const float* bm    = (const float*)d_in[15];
    float* out = (float*)d_out;

    void *pAq, *pAv, *pQadj, *pVadj, *pqh, *pkh, *pvh, *pao, *pmw;
    cudaGetSymbolAddress(&pAq,   g_Aq);
    cudaGetSymbolAddress(&pAv,   g_Av);
    cudaGetSymbolAddress(&pQadj, g_Qadj);
    cudaGetSymbolAddress(&pVadj, g_Vadj);
    cudaGetSymbolAddress(&pqh,   g_qh);
    cudaGetSymbolAddress(&pkh,   g_kh);
    cudaGetSymbolAddress(&pvh,   g_vh);
    cudaGetSymbolAddress(&pao,   g_ao);
    cudaGetSymbolAddress(&pmw,   g_mw);

    // mask pack (independent, kick off first)
    mask_pack_kernel<<<(B_ * S_ * (S_ / 32)) / 256, 256>>>(mask, (unsigned*)pmw);

    // LoRA down
    lora_down_kernel<<<N_ / 8, 256>>>(query, lAq, (float*)pAq);
    lora_down_kernel<<<N_ / 8, 256>>>(value, lAv, (float*)pAv);

    // LoRA up + residual
    lora_up_kernel<<<(N_ * D_) / 256, 256>>>(query, (const float*)pAq, lBq, (float*)pQadj);
    lora_up_kernel<<<(N_ * D_) / 256, 256>>>(value, (const float*)pAv, lBv, (float*)pVadj);

    // Projections (reference's stream swap preserved)
    cudaFuncSetAttribute(gemm_tf32_kernel, cudaFuncAttributeMaxDynamicSharedMemorySize, GEMM_SMEM);
    dim3 gg(N_ / 128, D_ / 64);
    gemm_tf32_kernel<<<gg, 256, GEMM_SMEM>>>((const float*)pQadj, Wv, bv, (float*)pvh, 1.0f,   1);
    gemm_tf32_kernel<<<gg, 256, GEMM_SMEM>>>(key,                 Wk, bk, (float*)pkh, 1.0f,   1);
    gemm_tf32_kernel<<<gg, 256, GEMM_SMEM>>>((const float*)pVadj, Wq, bq, (float*)pqh, 0.125f, 1);

    // Flash attention (tensor cores) -> g_ao [B,S,D]
    cudaFuncSetAttribute(attn_tc_kernel, cudaFuncAttributeMaxDynamicSharedMemorySize, ATTN_SMEM);
    attn_tc_kernel<<<dim3(S_ / 128, H_, B_), 256, ATTN_SMEM>>>((const unsigned*)pmw, (float*)pao);

    // Final: out = g_ao @ Wm^T + bm
    gemm_tf32_kernel<<<gg, 256, GEMM_SMEM>>>((const float*)pao, Wm, bm, out, 1.0f, 0);
}

// round 4
// speedup vs baseline: 1.0824x; 1.0824x over previous
#include <cuda_runtime.h>

#define B_ 2
#define S_ 2048
#define D_ 768
#define H_ 12
#define DK_ 64
#define R_ 8
#define N_ 4096   // B_*S_

// ---------------- scratch (static device globals; no allocation) ----------------
__device__ float g_Aq[N_ * R_];
__device__ float g_Av[N_ * R_];
__device__ float g_Qadj[(size_t)N_ * D_];
__device__ float g_Vadj[(size_t)N_ * D_];
__device__ float g_qh[(size_t)N_ * D_];   // [B,H,S,DK], pre-scaled by 1/8
__device__ float g_kh[(size_t)N_ * D_];   // [B,H,S,DK]
__device__ float g_vh[(size_t)N_ * D_];   // [B,H,S,DK]
__device__ float g_ao[(size_t)N_ * D_];   // [B,S,D] attention output
__device__ unsigned g_mw[B_ * S_ * (S_ / 32)];  // packed mask bits

// ---------------- tf32 helpers ---------------------------------------------------
__device__ __forceinline__ unsigned f2tf(float f) {
    unsigned u;
    asm("cvt.rna.tf32.f32 %0, %1;" : "=r"(u) : "f"(f));
    return u;
}
__device__ __forceinline__ uint4 cvt4(float4 v) {
    return make_uint4(f2tf(v.x), f2tf(v.y), f2tf(v.z), f2tf(v.w));
}
__device__ __forceinline__ void mma8(float* c, const unsigned* a, const unsigned* b) {
    asm volatile(
        "mma.sync.aligned.m16n8k8.row.col.f32.tf32.tf32.f32 "
        "{%0,%1,%2,%3}, {%4,%5,%6,%7}, {%8,%9}, {%0,%1,%2,%3};"
        : "+f"(c[0]), "+f"(c[1]), "+f"(c[2]), "+f"(c[3])
        : "r"(a[0]), "r"(a[1]), "r"(a[2]), "r"(a[3]), "r"(b[0]), "r"(b[1]));
}

// ---------------- K0: x[N,768] @ A[768,8] -> out[N,8]  (one warp per row) -------
__global__ void lora_down_kernel(const float* __restrict__ x,
                                 const float* __restrict__ A,
                                 float* __restrict__ out) {
    int warp = (blockIdx.x * blockDim.x + threadIdx.x) >> 5;
    int lane = threadIdx.x & 31;
    if (warp >= N_) return;
    float acc[8] = {0.f,0.f,0.f,0.f,0.f,0.f,0.f,0.f};
    const float* xr = x + (size_t)warp * D_;
    for (int k = lane; k < D_; k += 32) {
        float xv = xr[k];
        float4 a0 = *(const float4*)(A + k * 8);
        float4 a1 = *(const float4*)(A + k * 8 + 4);
        acc[0] += xv * a0.x; acc[1] += xv * a0.y; acc[2] += xv * a0.z; acc[3] += xv * a0.w;
        acc[4] += xv * a1.x; acc[5] += xv * a1.y; acc[6] += xv * a1.z; acc[7] += xv * a1.w;
    }
    #pragma unroll
    for (int r = 0; r < 8; r++) {
        #pragma unroll
        for (int off = 16; off > 0; off >>= 1)
            acc[r] += __shfl_xor_sync(0xffffffffu, acc[r], off);
    }
    if (lane == 0) {
        float4* o = (float4*)(out + (size_t)warp * 8);
        o[0] = make_float4(acc[0], acc[1], acc[2], acc[3]);
        o[1] = make_float4(acc[4], acc[5], acc[6], acc[7]);
    }
}

// -------- K1: out = x + Ar[N,8] @ Bm[8,768]  -------------------------------------
__global__ void lora_up_kernel(const float* __restrict__ x,
                               const float* __restrict__ Ar,
                               const float* __restrict__ Bm,
                               float* __restrict__ out) {
    int i = blockIdx.x * blockDim.x + threadIdx.x;
    int row = i / D_;
    int col = i - row * D_;
    float4 a0 = *(const float4*)(Ar + (size_t)row * 8);
    float4 a1 = *(const float4*)(Ar + (size_t)row * 8 + 4);
    float s = x[i];
    s += a0.x * Bm[0 * D_ + col];
    s += a0.y * Bm[1 * D_ + col];
    s += a0.z * Bm[2 * D_ + col];
    s += a0.w * Bm[3 * D_ + col];
    s += a1.x * Bm[4 * D_ + col];
    s += a1.y * Bm[5 * D_ + col];
    s += a1.z * Bm[6 * D_ + col];
    s += a1.w * Bm[7 * D_ + col];
    out[i] = s;
}

// -------- K1b: pack mask ints into bits ------------------------------------------
__global__ void mask_pack_kernel(const int* __restrict__ mask,
                                 unsigned* __restrict__ mw) {
    int w = blockIdx.x * blockDim.x + threadIdx.x;
    const int4* mp = (const int4*)(mask + (size_t)w * 32);
    unsigned bits = 0;
    #pragma unroll
    for (int j = 0; j < 8; j++) {
        int4 v = mp[j];
        bits |= (v.x != 0 ? 1u : 0u) << (j * 4 + 0);
        bits |= (v.y != 0 ? 1u : 0u) << (j * 4 + 1);
        bits |= (v.z != 0 ? 1u : 0u) << (j * 4 + 2);
        bits |= (v.w != 0 ? 1u : 0u) << (j * 4 + 3);
    }
    mw[w] = bits;
}

// ---- K2: tf32 GEMM  C = scale*(A @ W^T + bias) ----------------------------------
// 256 threads = 8 warps (4m x 2n), BM=128, BN=64, BK=32, warp tile 32x32.
// Register-prefetch double buffering; smem holds tf32 (convert once at STS).
#define GST 36
__global__ void __launch_bounds__(256)
gemm_tf32_kernel(const float* __restrict__ A, const float* __restrict__ W,
                 const float* __restrict__ bias, float* __restrict__ C,
                 float scale, int headPermute) {
    __shared__ unsigned As[2][128 * GST];
    __shared__ unsigned Bs[2][64 * GST];
    int tid = threadIdx.x;
    int warp = tid >> 5, lane = tid & 31;
    int wm = warp >> 1, wn = warp & 1;
    int lr = lane >> 2, lc = lane & 3;
    int i0 = blockIdx.x * 128, n0 = blockIdx.y * 64;
    int lrow = tid >> 3, lc4 = (tid & 7) << 2;

    float c[2][4][4];
    #pragma unroll
    for (int mi = 0; mi < 2; mi++)
        #pragma unroll
        for (int ni = 0; ni < 4; ni++)
            #pragma unroll
            for (int q = 0; q < 4; q++) c[mi][ni][q] = 0.f;

    float4 ra[4], rb[2];
    // tile 0: load -> cvt -> store
    #pragma unroll
    for (int p = 0; p < 4; p++)
        ra[p] = *(const float4*)(A + (size_t)(i0 + lrow + p * 32) * D_ + lc4);
    #pragma unroll
    for (int p = 0; p < 2; p++)
        rb[p] = *(const float4*)(W + (size_t)(n0 + lrow + p * 32) * D_ + lc4);
    #pragma unroll
    for (int p = 0; p < 4; p++)
        *(uint4*)&As[0][(lrow + p * 32) * GST + lc4] = cvt4(ra[p]);
    #pragma unroll
    for (int p = 0; p < 2; p++)
        *(uint4*)&Bs[0][(lrow + p * 32) * GST + lc4] = cvt4(rb[p]);
    __syncthreads();

    for (int it = 0; it < 24; it++) {
        int buf = it & 1;
        if (it < 23) {
            int k0 = (it + 1) * 32;
            #pragma unroll
            for (int p = 0; p < 4; p++)
                ra[p] = *(const float4*)(A + (size_t)(i0 + lrow + p * 32) * D_ + k0 + lc4);
            #pragma unroll
            for (int p = 0; p < 2; p++)
                rb[p] = *(const float4*)(W + (size_t)(n0 + lrow + p * 32) * D_ + k0 + lc4);
        }

        const unsigned* Ab = As[buf];
        const unsigned* Bb = Bs[buf];
        #pragma unroll
        for (int kk = 0; kk < 32; kk += 8) {
            unsigned a[2][4], bf[4][2];
            #pragma unroll
            for (int mi = 0; mi < 2; mi++) {
                int r = wm * 32 + mi * 16 + lr;
                a[mi][0] = Ab[r * GST + kk + lc];
                a[mi][1] = Ab[(r + 8) * GST + kk + lc];
                a[mi][2] = Ab[r * GST + kk + lc + 4];
                a[mi][3] = Ab[(r + 8) * GST + kk + lc + 4];
            }
            #pragma unroll
            for (int ni = 0; ni < 4; ni++) {
                int n = wn * 32 + ni * 8 + lr;
                bf[ni][0] = Bb[n * GST + kk + lc];
                bf[ni][1] = Bb[n * GST + kk + lc + 4];
            }
            #pragma unroll
            for (int mi = 0; mi < 2; mi++)
                #pragma unroll
                for (int ni = 0; ni < 4; ni++)
                    mma8(c[mi][ni], a[mi], bf[ni]);
        }

        if (it < 23) {
            int nb = buf ^ 1;
            #pragma unroll
            for (int p = 0; p < 4; p++)
                *(uint4*)&As[nb][(lrow + p * 32) * GST + lc4] = cvt4(ra[p]);
            #pragma unroll
            for (int p = 0; p < 2; p++)
                *(uint4*)&Bs[nb][(lrow + p * 32) * GST + lc4] = cvt4(rb[p]);
        }
        __syncthreads();
    }

    #pragma unroll
    for (int mi = 0; mi < 2; mi++) {
        #pragma unroll
        for (int ni = 0; ni < 4; ni++) {
            int i = i0 + wm * 32 + mi * 16 + lr;
            int j = n0 + wn * 32 + ni * 8 + 2 * lc;
            float b0 = bias[j], b1 = bias[j + 1];
            float2 o0 = make_float2(scale * (c[mi][ni][0] + b0), scale * (c[mi][ni][1] + b1));
            float2 o1 = make_float2(scale * (c[mi][ni][2] + b0), scale * (c[mi][ni][3] + b1));
            if (headPermute) {
                int bb = i >> 11, s = i & 2047;
                int hh = j >> 6, dk = j & 63;
                *(float2*)(C + (((size_t)(bb * H_ + hh)) * S_ + s) * DK_ + dk) = o0;
                *(float2*)(C + (((size_t)(bb * H_ + hh)) * S_ + (s + 8)) * DK_ + dk) = o1;
            } else {
                *(float2*)(C + (size_t)i * D_ + j) = o0;
                *(float2*)(C + (size_t)(i + 8) * D_ + j) = o1;
            }
        }
    }
}

// ---------------- K3: flash attention, tf32 mma ----------------------------------
// 256 threads = 8 warps, warp strip 16 q-rows, BM=128, KV tile 64.
// smem tf32 (convert at store); single buffer; 2 blocks/SM cover latency.
#define AST 68
#define ATTN_SMEM ((128 * AST + 64 * AST + 64 * AST + 128 * AST) * 4)
__global__ void __launch_bounds__(256, 2)
attn_tc_kernel(const unsigned* __restrict__ mw, float* __restrict__ out) {
    extern __shared__ unsigned sm[];
    unsigned* Qs = sm;                   // [128][AST]
    unsigned* Ks = Qs + 128 * AST;       // [64][AST]
    unsigned* Vs = Ks + 64 * AST;        // [64][AST]
    unsigned* Ps = Vs + 64 * AST;        // [128][AST]

    int tid = threadIdx.x, warp = tid >> 5, lane = tid & 31;
    int lr = lane >> 2, lc = lane & 3;
    int rb = warp * 16;
    int qb = blockIdx.x, h = blockIdx.y, b = blockIdx.z;
    int q0 = qb * 128, bh = b * H_ + h;

    const float* qg = g_qh + ((size_t)bh * S_ + q0) * DK_;
    const float* kg = g_kh + (size_t)bh * S_ * DK_;
    const float* vg = g_vh + (size_t)bh * S_ * DK_;

    int lrow = tid >> 4, lc4 = (tid & 15) << 2;

    // Q -> smem (tf32), 128 rows
    #pragma unroll
    for (int p = 0; p < 8; p++) {
        int row = lrow + p * 16;
        *(uint4*)&Qs[row * AST + lc4] = cvt4(*(const float4*)(qg + (size_t)row * DK_ + lc4));
    }

    float o[8][4];
    float m[2], l[2];
    m[0] = -1e30f; m[1] = -1e30f; l[0] = 0.f; l[1] = 0.f;
    #pragma unroll
    for (int ni = 0; ni < 8; ni++)
        #pragma unroll
        for (int q = 0; q < 4; q++) o[ni][q] = 0.f;

    for (int kb = 0; kb < S_ / 64; kb++) {
        int k0 = kb * 64;
        __syncthreads();   // previous PV reads done before overwrite
        #pragma unroll
        for (int p = 0; p < 4; p++) {
            int row = lrow + p * 16;
            *(uint4*)&Ks[row * AST + lc4] =
                cvt4(*(const float4*)(kg + (size_t)(k0 + row) * DK_ + lc4));
            *(uint4*)&Vs[row * AST + lc4] =
                cvt4(*(const float4*)(vg + (size_t)(k0 + row) * DK_ + lc4));
        }
        __syncthreads();

        // --- S = Q K^T (q pre-scaled by 1/8) ---
        float s[8][4];
        #pragma unroll
        for (int ni = 0; ni < 8; ni++)
            #pragma unroll
            for (int q = 0; q < 4; q++) s[ni][q] = 0.f;

        #pragma unroll
        for (int kk = 0; kk < 64; kk += 8) {
            unsigned a[4], bf[8][2];
            a[0] = Qs[(rb + lr) * AST + kk + lc];
            a[1] = Qs[(rb + 8 + lr) * AST + kk + lc];
            a[2] = Qs[(rb + lr) * AST + kk + lc + 4];
            a[3] = Qs[(rb + 8 + lr) * AST + kk + lc + 4];
            #pragma unroll
            for (int ni = 0; ni < 8; ni++) {
                int n = ni * 8 + lr;
                bf[ni][0] = Ks[n * AST + kk + lc];
                bf[ni][1] = Ks[n * AST + kk + lc + 4];
            }
            #pragma unroll
            for (int ni = 0; ni < 8; ni++)
                mma8(s[ni], a, bf[ni]);
        }

        // --- mask + online softmax + write P (tf32) to smem ---
        #pragma unroll
        for (int hh = 0; hh < 2; hh++) {
            int rloc = rb + hh * 8 + lr;
            int grow = q0 + rloc;
            uint2 w = *(const uint2*)(mw + ((size_t)b * S_ + grow) * (S_ / 32) + kb * 2);
            float rmax = -1e30f;
            #pragma unroll
            for (int ni = 0; ni < 8; ni++) {
                int col = ni * 8 + 2 * lc;
                unsigned ws = (col < 32) ? w.x : w.y;
                int bit = col & 31;
                float* sp = &s[ni][hh * 2];
                if (!((ws >> bit) & 1u))       sp[0] = -1e9f;
                if (!((ws >> (bit + 1)) & 1u)) sp[1] = -1e9f;
                rmax = fmaxf(rmax, fmaxf(sp[0], sp[1]));
            }
            rmax = fmaxf(rmax, __shfl_xor_sync(0xffffffffu, rmax, 1));
            rmax = fmaxf(rmax, __shfl_xor_sync(0xffffffffu, rmax, 2));
            float mn = fmaxf(m[hh], rmax);
            float corr = __expf(m[hh] - mn);
            m[hh] = mn;
            float rs = 0.f;
            #pragma unroll
            for (int ni = 0; ni < 8; ni++) {
                float* sp = &s[ni][hh * 2];
                float p0 = __expf(sp[0] - mn);
                float p1 = __expf(sp[1] - mn);
                rs += p0 + p1;
                int col = ni * 8 + 2 * lc;
                *(uint2*)&Ps[rloc * AST + col] = make_uint2(f2tf(p0), f2tf(p1));
                o[ni][hh * 2]     *= corr;
                o[ni][hh * 2 + 1] *= corr;
            }
            rs += __shfl_xor_sync(0xffffffffu, rs, 1);
            rs += __shfl_xor_sync(0xffffffffu, rs, 2);
            l[hh] = l[hh] * corr + rs;
        }
        __syncwarp();   // Ps rows are warp-private; order STS before LDS in-warp

        // --- O += P @ V ---
        #pragma unroll
        for (int kk = 0; kk < 64; kk += 8) {
            unsigned a[4], bf[8][2];
            a[0] = Ps[(rb + lr) * AST + kk + lc];
            a[1] = Ps[(rb + 8 + lr) * AST + kk + lc];
            a[2] = Ps[(rb + lr) * AST + kk + lc + 4];
            a[3] = Ps[(rb + 8 + lr) * AST + kk + lc + 4];
            #pragma unroll
            for (int ni = 0; ni < 8; ni++) {
                int n = ni * 8 + lr;
                bf[ni][0] = Vs[(kk + lc) * AST + n];
                bf[ni][1] = Vs[(kk + lc + 4) * AST + n];
            }
            #pragma unroll
            for (int ni = 0; ni < 8; ni++)
                mma8(o[ni], a, bf[ni]);
        }
    }

    // --- epilogue: O / l -> out [B,S,D] ---
    #pragma unroll
    for (int hh = 0; hh < 2; hh++) {
        float inv = 1.0f / l[hh];
        int grow = q0 + rb + hh * 8 + lr;
        #pragma unroll
        for (int ni = 0; ni < 8; ni++) {
            int col = ni * 8 + 2 * lc;
            float2 ov = make_float2(o[ni][hh * 2] * inv, o[ni][hh * 2 + 1] * inv);
            *(float2*)(out + ((size_t)(b * S_ + grow)) * D_ + h * DK_ + col) = ov;
        }
    }
}

// --------------------------------- host ------------------------------------------
extern "C" void kernel_launch(void* const* d_in, const int* in_sizes, int n_in,
                              void* d_out, int out_size) {
    const float* query = (const float*)d_in[0];
    const float* key   = (const float*)d_in[1];
    const float* value = (const float*)d_in[2];
    const int*   mask  = (const int*)d_in[3];
    const float* lAq   = (const float*)d_in[4];
    const float* lBq   = (const float*)d_in[5];
    const float* lAv   = (const float*)d_in[6];
    const float* lBv   = (const float*)d_in[7];
    const float* Wq    = (const float*)d_in[8];
    const float* bq    = (const float*)d_in[9];
    const float* Wk    = (const float*)d_in[10];
    const float* bk    = (const float*)d_in[11];
    const float* Wv    = (const float*)d_in[12];
    const float* bv    = (const float*)d_in[13];
    const float* Wm    = (const float*)d_in[14];
    const float* bm    = (const float*)d_in[15];
    float* out = (float*)d_out;

    void *pAq, *pAv, *pQadj, *pVadj, *pqh, *pkh, *pvh, *pao, *pmw;
    cudaGetSymbolAddress(&pAq,   g_Aq);
    cudaGetSymbolAddress(&pAv,   g_Av);
    cudaGetSymbolAddress(&pQadj, g_Qadj);
    cudaGetSymbolAddress(&pVadj, g_Vadj);
    cudaGetSymbolAddress(&pqh,   g_qh);
    cudaGetSymbolAddress(&pkh,   g_kh);
    cudaGetSymbolAddress(&pvh,   g_vh);
    cudaGetSymbolAddress(&pao,   g_ao);
    cudaGetSymbolAddress(&pmw,   g_mw);

    // mask pack (independent, kick off first)
    mask_pack_kernel<<<(B_ * S_ * (S_ / 32)) / 256, 256>>>(mask, (unsigned*)pmw);

    // LoRA down
    lora_down_kernel<<<N_ / 8, 256>>>(query, lAq, (float*)pAq);
    lora_down_kernel<<<N_ / 8, 256>>>(value, lAv, (float*)pAv);

    // LoRA up + residual
    lora_up_kernel<<<(N_ * D_) / 256, 256>>>(query, (const float*)pAq, lBq, (float*)pQadj);
    lora_up_kernel<<<(N_ * D_) / 256, 256>>>(value, (const float*)pAv, lBv, (float*)pVadj);

    // Projections (reference's stream swap preserved)
    dim3 gg(N_ / 128, D_ / 64);
    gemm_tf32_kernel<<<gg, 256>>>((const float*)pQadj, Wv, bv, (float*)pvh, 1.0f,   1);
    gemm_tf32_kernel<<<gg, 256>>>(key,                 Wk, bk, (float*)pkh, 1.0f,   1);
    gemm_tf32_kernel<<<gg, 256>>>((const float*)pVadj, Wq, bq, (float*)pqh, 0.125f, 1);

    // Flash attention (tensor cores) -> g_ao [B,S,D]
    cudaFuncSetAttribute(attn_tc_kernel, cudaFuncAttributeMaxDynamicSharedMemorySize, ATTN_SMEM);
    attn_tc_kernel<<<dim3(S_ / 128, H_, B_), 256, ATTN_SMEM>>>((const unsigned*)pmw, (float*)pao);

    // Final: out = g_ao @ Wm^T + bm
    gemm_tf32_kernel<<<gg, 256>>>((const float*)pao, Wm, bm, out, 1.0f, 0);
}

// round 6
// speedup vs baseline: 1.2511x; 1.1558x over previous
#include <cuda_runtime.h>
#include <cstdint>

#define B_ 2
#define S_ 2048
#define D_ 768
#define H_ 12
#define DK_ 64
#define R_ 8
#define N_ 4096   // B_*S_

// ---------------- scratch (static device globals; no allocation) ----------------
__device__ float g_Aq[N_ * R_];
__device__ float g_Av[N_ * R_];
__device__ float g_Qadj[(size_t)N_ * D_];
__device__ float g_Vadj[(size_t)N_ * D_];
__device__ float g_qh[(size_t)N_ * D_];   // [B,H,S,DK], pre-scaled by 1/8
__device__ float g_kh[(size_t)N_ * D_];   // [B,H,S,DK]
__device__ float g_vh[(size_t)N_ * D_];   // [B,H,S,DK]
__device__ float g_ao[(size_t)N_ * D_];   // [B,S,D] attention output
__device__ unsigned g_mw[B_ * S_ * (S_ / 32)];  // packed mask bits

// ---------------- fp16 helpers ----------------------------------------------------
// pack two floats into half2 word: lo = a, hi = b
__device__ __forceinline__ unsigned f2h2(float a, float b) {
    unsigned r;
    asm("cvt.rn.f16x2.f32 %0, %1, %2;" : "=r"(r) : "f"(b), "f"(a));
    return r;
}
__device__ __forceinline__ uint2 cvt4h(float4 v) {
    return make_uint2(f2h2(v.x, v.y), f2h2(v.z, v.w));
}
// D(f32 m16n8) += A(f16 m16k16) * B(f16 k16n8)
__device__ __forceinline__ void mma16(float* c, const unsigned* a, const unsigned* b) {
    asm volatile(
        "mma.sync.aligned.m16n8k16.row.col.f32.f16.f16.f32 "
        "{%0,%1,%2,%3}, {%4,%5,%6,%7}, {%8,%9}, {%0,%1,%2,%3};"
        : "+f"(c[0]), "+f"(c[1]), "+f"(c[2]), "+f"(c[3])
        : "r"(a[0]), "r"(a[1]), "r"(a[2]), "r"(a[3]), "r"(b[0]), "r"(b[1]));
}

// ---------------- K0: x[N,768] @ A[768,8] -> out[N,8]  (one warp per row) -------
__global__ void lora_down_kernel(const float* __restrict__ x,
                                 const float* __restrict__ A,
                                 float* __restrict__ out) {
    int warp = (blockIdx.x * blockDim.x + threadIdx.x) >> 5;
    int lane = threadIdx.x & 31;
    if (warp >= N_) return;
    float acc[8] = {0.f,0.f,0.f,0.f,0.f,0.f,0.f,0.f};
    const float* xr = x + (size_t)warp * D_;
    for (int k = lane; k < D_; k += 32) {
        float xv = xr[k];
        float4 a0 = *(const float4*)(A + k * 8);
        float4 a1 = *(const float4*)(A + k * 8 + 4);
        acc[0] += xv * a0.x; acc[1] += xv * a0.y; acc[2] += xv * a0.z; acc[3] += xv * a0.w;
        acc[4] += xv * a1.x; acc[5] += xv * a1.y; acc[6] += xv * a1.z; acc[7] += xv * a1.w;
    }
    #pragma unroll
    for (int r = 0; r < 8; r++) {
        #pragma unroll
        for (int off = 16; off > 0; off >>= 1)
            acc[r] += __shfl_xor_sync(0xffffffffu, acc[r], off);
    }
    if (lane == 0) {
        float4* o = (float4*)(out + (size_t)warp * 8);
        o[0] = make_float4(acc[0], acc[1], acc[2], acc[3]);
        o[1] = make_float4(acc[4], acc[5], acc[6], acc[7]);
    }
}

// -------- K1: out = x + Ar[N,8] @ Bm[8,768]  -------------------------------------
__global__ void lora_up_kernel(const float* __restrict__ x,
                               const float* __restrict__ Ar,
                               const float* __restrict__ Bm,
                               float* __restrict__ out) {
    int i = blockIdx.x * blockDim.x + threadIdx.x;
    int row = i / D_;
    int col = i - row * D_;
    float4 a0 = *(const float4*)(Ar + (size_t)row * 8);
    float4 a1 = *(const float4*)(Ar + (size_t)row * 8 + 4);
    float s = x[i];
    s += a0.x * Bm[0 * D_ + col];
    s += a0.y * Bm[1 * D_ + col];
    s += a0.z * Bm[2 * D_ + col];
    s += a0.w * Bm[3 * D_ + col];
    s += a1.x * Bm[4 * D_ + col];
    s += a1.y * Bm[5 * D_ + col];
    s += a1.z * Bm[6 * D_ + col];
    s += a1.w * Bm[7 * D_ + col];
    out[i] = s;
}

// -------- K1b: pack mask ints into bits ------------------------------------------
__global__ void mask_pack_kernel(const int* __restrict__ mask,
                                 unsigned* __restrict__ mw) {
    int w = blockIdx.x * blockDim.x + threadIdx.x;
    const int4* mp = (const int4*)(mask + (size_t)w * 32);
    unsigned bits = 0;
    #pragma unroll
    for (int j = 0; j < 8; j++) {
        int4 v = mp[j];
        bits |= (v.x != 0 ? 1u : 0u) << (j * 4 + 0);
        bits |= (v.y != 0 ? 1u : 0u) << (j * 4 + 1);
        bits |= (v.z != 0 ? 1u : 0u) << (j * 4 + 2);
        bits |= (v.w != 0 ? 1u : 0u) << (j * 4 + 3);
    }
    mw[w] = bits;
}

// ---- K2: fp16 HMMA GEMM  C = scale*(A @ W^T + bias) -----------------------------
// 256 threads = 8 warps (4m x 2n), BM=128, BN=64, BK=32, warp tile 32x32.
// smem stores half2 words; register-prefetch double buffering.
#define GSTW 20   // 32-bit words per 32-half row (16 + 4 pad)
__global__ void __launch_bounds__(256)
gemm_h_kernel(const float* __restrict__ A, const float* __restrict__ W,
              const float* __restrict__ bias, float* __restrict__ C,
              float scale, int headPermute) {
    __shared__ unsigned As[2][128 * GSTW];
    __shared__ unsigned Bs[2][64 * GSTW];
    int tid = threadIdx.x;
    int warp = tid >> 5, lane = tid & 31;
    int wm = warp >> 1, wn = warp & 1;
    int lr = lane >> 2, lc = lane & 3;
    int i0 = blockIdx.x * 128, n0 = blockIdx.y * 64;

    // load mapping: A row = tid/2, 16 floats at (tid&1)*16; B row = tid/4, 8 floats
    int arow = tid >> 1, akf = (tid & 1) << 4;   // float offset
    int brow = tid >> 2, bkf = (tid & 3) << 3;
    const float* Ap = A + (size_t)(i0 + arow) * D_ + akf;
    const float* Wp = W + (size_t)(n0 + brow) * D_ + bkf;
    int akw = akf >> 1, bkw = bkf >> 1;          // word offsets

    float c[2][4][4];
    #pragma unroll
    for (int mi = 0; mi < 2; mi++)
        #pragma unroll
        for (int ni = 0; ni < 4; ni++)
            #pragma unroll
            for (int q = 0; q < 4; q++) c[mi][ni][q] = 0.f;

    float4 ra[4], rb[2];
    #pragma unroll
    for (int p = 0; p < 4; p++) ra[p] = *(const float4*)(Ap + 4 * p);
    #pragma unroll
    for (int p = 0; p < 2; p++) rb[p] = *(const float4*)(Wp + 4 * p);
    #pragma unroll
    for (int p = 0; p < 4; p++)
        *(uint2*)&As[0][arow * GSTW + akw + 2 * p] = cvt4h(ra[p]);
    #pragma unroll
    for (int p = 0; p < 2; p++)
        *(uint2*)&Bs[0][brow * GSTW + bkw + 2 * p] = cvt4h(rb[p]);
    __syncthreads();

    for (int it = 0; it < 24; it++) {
        int buf = it & 1;
        if (it < 23) {
            int k0 = (it + 1) * 32;
            #pragma unroll
            for (int p = 0; p < 4; p++) ra[p] = *(const float4*)(Ap + k0 + 4 * p);
            #pragma unroll
            for (int p = 0; p < 2; p++) rb[p] = *(const float4*)(Wp + k0 + 4 * p);
        }

        const unsigned* Ab = As[buf];
        const unsigned* Bb = Bs[buf];
        #pragma unroll
        for (int kk2 = 0; kk2 < 16; kk2 += 8) {   // two k16 steps (word offsets)
            unsigned a[2][4], bf[4][2];
            #pragma unroll
            for (int mi = 0; mi < 2; mi++) {
                int r = wm * 32 + mi * 16 + lr;
                a[mi][0] = Ab[r * GSTW + kk2 + lc];
                a[mi][1] = Ab[(r + 8) * GSTW + kk2 + lc];
                a[mi][2] = Ab[r * GSTW + kk2 + lc + 4];
                a[mi][3] = Ab[(r + 8) * GSTW + kk2 + lc + 4];
            }
            #pragma unroll
            for (int ni = 0; ni < 4; ni++) {
                int n = wn * 32 + ni * 8 + lr;
                bf[ni][0] = Bb[n * GSTW + kk2 + lc];
                bf[ni][1] = Bb[n * GSTW + kk2 + lc + 4];
            }
            #pragma unroll
            for (int mi = 0; mi < 2; mi++)
                #pragma unroll
                for (int ni = 0; ni < 4; ni++)
                    mma16(c[mi][ni], a[mi], bf[ni]);
        }

        if (it < 23) {
            int nb = buf ^ 1;
            #pragma unroll
            for (int p = 0; p < 4; p++)
                *(uint2*)&As[nb][arow * GSTW + akw + 2 * p] = cvt4h(ra[p]);
            #pragma unroll
            for (int p = 0; p < 2; p++)
                *(uint2*)&Bs[nb][brow * GSTW + bkw + 2 * p] = cvt4h(rb[p]);
        }
        __syncthreads();
    }

    #pragma unroll
    for (int mi = 0; mi < 2; mi++) {
        #pragma unroll
        for (int ni = 0; ni < 4; ni++) {
            int i = i0 + wm * 32 + mi * 16 + lr;
            int j = n0 + wn * 32 + ni * 8 + 2 * lc;
            float b0 = bias[j], b1 = bias[j + 1];
            float2 o0 = make_float2(scale * (c[mi][ni][0] + b0), scale * (c[mi][ni][1] + b1));
            float2 o1 = make_float2(scale * (c[mi][ni][2] + b0), scale * (c[mi][ni][3] + b1));
            if (headPermute) {
                int bb = i >> 11, s = i & 2047;
                int hh = j >> 6, dk = j & 63;
                *(float2*)(C + (((size_t)(bb * H_ + hh)) * S_ + s) * DK_ + dk) = o0;
                *(float2*)(C + (((size_t)(bb * H_ + hh)) * S_ + (s + 8)) * DK_ + dk) = o1;
            } else {
                *(float2*)(C + (size_t)i * D_ + j) = o0;
                *(float2*)(C + (size_t)(i + 8) * D_ + j) = o1;
            }
        }
    }
}

// ---------------- K3: flash attention, fp16 HMMA ----------------------------------
// 256 threads = 8 warps, warp strip 16 q-rows, BM=128, KV tile 64.
// Q/K/P stored as half2 words; V stored TRANSPOSED (pair-packed) for PV B-frags.
#define ASTW 36   // words per 64-half row (32 + 4 pad)
#define ATTN_SMEM ((128 * ASTW + 64 * ASTW + 64 * ASTW + 128 * ASTW) * 4)
__global__ void __launch_bounds__(256)
attn_h_kernel(const unsigned* __restrict__ mw, float* __restrict__ out) {
    extern __shared__ unsigned sm[];
    unsigned* Qs = sm;                    // [128][ASTW] q rows
    unsigned* Ks = Qs + 128 * ASTW;       // [64][ASTW]  k rows (dk contiguous)
    unsigned* Vt = Ks + 64 * ASTW;        // [64][ASTW]  dk rows, kv-pair words
    unsigned* Ps = Vt + 64 * ASTW;        // [128][ASTW] p rows

    int tid = threadIdx.x, warp = tid >> 5, lane = tid & 31;
    int lr = lane >> 2, lc = lane & 3;
    int rb = warp * 16;
    int qb = blockIdx.x, h = blockIdx.y, b = blockIdx.z;
    int q0 = qb * 128, bh = b * H_ + h;

    const float* qg = g_qh + ((size_t)bh * S_ + q0) * DK_;
    const float* kg = g_kh + (size_t)bh * S_ * DK_;
    const float* vg = g_vh + (size_t)bh * S_ * DK_;

    int lrow = tid >> 4, lcf = (tid & 15) << 2;   // per-row float4 slot
    int lcw = lcf >> 1;

    // Q -> smem half2, 128 rows x 64 cols
    #pragma unroll
    for (int p = 0; p < 8; p++) {
        int row = lrow + p * 16;
        *(uint2*)&Qs[row * ASTW + lcw] = cvt4h(*(const float4*)(qg + (size_t)row * DK_ + lcf));
    }

    float o[8][4];
    float m[2], l[2];
    m[0] = -1e30f; m[1] = -1e30f; l[0] = 0.f; l[1] = 0.f;
    #pragma unroll
    for (int ni = 0; ni < 8; ni++)
        #pragma unroll
        for (int q = 0; q < 4; q++) o[ni][q] = 0.f;

    for (int kb = 0; kb < S_ / 64; kb++) {
        int k0 = kb * 64;
        __syncthreads();
        // K rows (dk contiguous)
        #pragma unroll
        for (int p = 0; p < 4; p++) {
            int row = lrow + p * 16;
            *(uint2*)&Ks[row * ASTW + lcw] =
                cvt4h(*(const float4*)(kg + (size_t)(k0 + row) * DK_ + lcf));
        }
        // V transposed pair-packed: word Vt[dk][r2] = half2(V[2r2][dk], V[2r2+1][dk])
        #pragma unroll
        for (int p = 0; p < 2; p++) {
            int t = tid + p * 256;
            int r2 = t & 31, dk4 = (t >> 5) << 2;
            float4 va = *(const float4*)(vg + (size_t)(k0 + 2 * r2) * DK_ + dk4);
            float4 vb = *(const float4*)(vg + (size_t)(k0 + 2 * r2 + 1) * DK_ + dk4);
            Vt[(dk4 + 0) * ASTW + r2] = f2h2(va.x, vb.x);
            Vt[(dk4 + 1) * ASTW + r2] = f2h2(va.y, vb.y);
            Vt[(dk4 + 2) * ASTW + r2] = f2h2(va.z, vb.z);
            Vt[(dk4 + 3) * ASTW + r2] = f2h2(va.w, vb.w);
        }
        __syncthreads();

        // --- S = Q K^T (q pre-scaled by 1/8) ---
        float s[8][4];
        #pragma unroll
        for (int ni = 0; ni < 8; ni++)
            #pragma unroll
            for (int q = 0; q < 4; q++) s[ni][q] = 0.f;

        #pragma unroll
        for (int kk2 = 0; kk2 < 32; kk2 += 8) {   // four k16 steps (word offsets)
            unsigned a[4], bf[8][2];
            a[0] = Qs[(rb + lr) * ASTW + kk2 + lc];
            a[1] = Qs[(rb + 8 + lr) * ASTW + kk2 + lc];
            a[2] = Qs[(rb + lr) * ASTW + kk2 + lc + 4];
            a[3] = Qs[(rb + 8 + lr) * ASTW + kk2 + lc + 4];
            #pragma unroll
            for (int ni = 0; ni < 8; ni++) {
                int n = ni * 8 + lr;
                bf[ni][0] = Ks[n * ASTW + kk2 + lc];
                bf[ni][1] = Ks[n * ASTW + kk2 + lc + 4];
            }
            #pragma unroll
            for (int ni = 0; ni < 8; ni++)
                mma16(s[ni], a, bf[ni]);
        }

        // --- mask + online softmax + write P (half2) ---
        #pragma unroll
        for (int hh = 0; hh < 2; hh++) {
            int rloc = rb + hh * 8 + lr;
            int grow = q0 + rloc;
            uint2 w = *(const uint2*)(mw + ((size_t)b * S_ + grow) * (S_ / 32) + kb * 2);
            float rmax = -1e30f;
            #pragma unroll
            for (int ni = 0; ni < 8; ni++) {
                int col = ni * 8 + 2 * lc;
                unsigned ws = (col < 32) ? w.x : w.y;
                int bit = col & 31;
                float* sp = &s[ni][hh * 2];
                if (!((ws >> bit) & 1u))       sp[0] = -1e9f;
                if (!((ws >> (bit + 1)) & 1u)) sp[1] = -1e9f;
                rmax = fmaxf(rmax, fmaxf(sp[0], sp[1]));
            }
            rmax = fmaxf(rmax, __shfl_xor_sync(0xffffffffu, rmax, 1));
            rmax = fmaxf(rmax, __shfl_xor_sync(0xffffffffu, rmax, 2));
            float mn = fmaxf(m[hh], rmax);
            float corr = __expf(m[hh] - mn);
            m[hh] = mn;
            float rs = 0.f;
            #pragma unroll
            for (int ni = 0; ni < 8; ni++) {
                float* sp = &s[ni][hh * 2];
                float p0 = __expf(sp[0] - mn);
                float p1 = __expf(sp[1] - mn);
                rs += p0 + p1;
                Ps[rloc * ASTW + ni * 4 + lc] = f2h2(p0, p1);
                o[ni][hh * 2]     *= corr;
                o[ni][hh * 2 + 1] *= corr;
            }
            rs += __shfl_xor_sync(0xffffffffu, rs, 1);
            rs += __shfl_xor_sync(0xffffffffu, rs, 2);
            l[hh] = l[hh] * corr + rs;
        }
        __syncwarp();   // Ps rows are warp-private; order STS before LDS in-warp

        // --- O += P @ V  (B-frags from transposed V) ---
        #pragma unroll
        for (int kk2 = 0; kk2 < 32; kk2 += 8) {
            unsigned a[4], bf[8][2];
            a[0] = Ps[(rb + lr) * ASTW + kk2 + lc];
            a[1] = Ps[(rb + 8 + lr) * ASTW + kk2 + lc];
            a[2] = Ps[(rb + lr) * ASTW + kk2 + lc + 4];
            a[3] = Ps[(rb + 8 + lr) * ASTW + kk2 + lc + 4];
            #pragma unroll
            for (int ni = 0; ni < 8; ni++) {
                int n = ni * 8 + lr;                 // dk column
                bf[ni][0] = Vt[n * ASTW + kk2 + lc];
                bf[ni][1] = Vt[n * ASTW + kk2 + lc + 4];
            }
            #pragma unroll
            for (int ni = 0; ni < 8; ni++)
                mma16(o[ni], a, bf[ni]);
        }
    }

    // --- epilogue: O / l -> out [B,S,D] ---
    #pragma unroll
    for (int hh = 0; hh < 2; hh++) {
        float inv = 1.0f / l[hh];
        int grow = q0 + rb + hh * 8 + lr;
        #pragma unroll
        for (int ni = 0; ni < 8; ni++) {
            int col = ni * 8 + 2 * lc;
            float2 ov = make_float2(o[ni][hh * 2] * inv, o[ni][hh * 2 + 1] * inv);
            *(float2*)(out + ((size_t)(b * S_ + grow)) * D_ + h * DK_ + col) = ov;
        }
    }
}

// --------------------------------- host ------------------------------------------
extern "C" void kernel_launch(void* const* d_in, const int* in_sizes, int n_in,
                              void* d_out, int out_size) {
    const float* query = (const float*)d_in[0];
    const float* key   = (const float*)d_in[1];
    const float* value = (const float*)d_in[2];
    const int*   mask  = (const int*)d_in[3];
    const float* lAq   = (const float*)d_in[4];
    const float* lBq   = (const float*)d_in[5];
    const float* lAv   = (const float*)d_in[6];
    const float* lBv   = (const float*)d_in[7];
    const float* Wq    = (const float*)d_in[8];
    const float* bq    = (const float*)d_in[9];
    const float* Wk    = (const float*)d_in[10];
    const float* bk    = (const float*)d_in[11];
    const float* Wv    = (const float*)d_in[12];
    const float* bv    = (const float*)d_in[13];
    const float* Wm    = (const float*)d_in[14];
    const float* bm    = (const float*)d_in[15];
    float* out = (float*)d_out;

    void *pAq, *pAv, *pQadj, *pVadj, *pqh, *pkh, *pvh, *pao, *pmw;
    cudaGetSymbolAddress(&pAq,   g_Aq);
    cudaGetSymbolAddress(&pAv,   g_Av);
    cudaGetSymbolAddress(&pQadj, g_Qadj);
    cudaGetSymbolAddress(&pVadj, g_Vadj);
    cudaGetSymbolAddress(&pqh,   g_qh);
    cudaGetSymbolAddress(&pkh,   g_kh);
    cudaGetSymbolAddress(&pvh,   g_vh);
    cudaGetSymbolAddress(&pao,   g_ao);
    cudaGetSymbolAddress(&pmw,   g_mw);

    // mask pack (independent, kick off first)
    mask_pack_kernel<<<(B_ * S_ * (S_ / 32)) / 256, 256>>>(mask, (unsigned*)pmw);

    // LoRA down
    lora_down_kernel<<<N_ / 8, 256>>>(query, lAq, (float*)pAq);
    lora_down_kernel<<<N_ / 8, 256>>>(value, lAv, (float*)pAv);

    // LoRA up + residual
    lora_up_kernel<<<(N_ * D_) / 256, 256>>>(query, (const float*)pAq, lBq, (float*)pQadj);
    lora_up_kernel<<<(N_ * D_) / 256, 256>>>(value, (const float*)pAv, lBv, (float*)pVadj);

    // Projections (reference's stream swap preserved)
    dim3 gg(N_ / 128, D_ / 64);
    gemm_h_kernel<<<gg, 256>>>((const float*)pQadj, Wv, bv, (float*)pvh, 1.0f,   1);
    gemm_h_kernel<<<gg, 256>>>(key,                 Wk, bk, (float*)pkh, 1.0f,   1);
    gemm_h_kernel<<<gg, 256>>>((const float*)pVadj, Wq, bq, (float*)pqh, 0.125f, 1);

    // Flash attention (fp16 tensor cores) -> g_ao [B,S,D]
    cudaFuncSetAttribute(attn_h_kernel, cudaFuncAttributeMaxDynamicSharedMemorySize, ATTN_SMEM);
    attn_h_kernel<<<dim3(S_ / 128, H_, B_), 256, ATTN_SMEM>>>((const unsigned*)pmw, (float*)pao);

    // Final: out = g_ao @ Wm^T + bm
    gemm_h_kernel<<<gg, 256>>>((const float*)pao, Wm, bm, out, 1.0f, 0);
}

// round 7
// speedup vs baseline: 1.3459x; 1.0758x over previous
#include <cuda_runtime.h>
#include <cstdint>

#define B_ 2
#define S_ 2048
#define D_ 768
#define H_ 12
#define DK_ 64
#define R_ 8
#define N_ 4096   // B_*S_

// ---------------- scratch (static device globals; no allocation) ----------------
__device__ float g_Aq[N_ * R_];
__device__ float g_Av[N_ * R_];
__device__ float g_Qadj[(size_t)N_ * D_];
__device__ float g_Vadj[(size_t)N_ * D_];
__device__ float g_qh[(size_t)N_ * D_];   // [B,H,S,DK], pre-scaled by 1/8
__device__ float g_kh[(size_t)N_ * D_];   // [B,H,S,DK]
__device__ float g_vh[(size_t)N_ * D_];   // [B,H,S,DK]
__device__ float g_ao[(size_t)N_ * D_];   // [B,S,D] attention output
__device__ unsigned g_mw[B_ * S_ * (S_ / 32)];  // packed mask bits

// ---------------- fp16 helpers ----------------------------------------------------
__device__ __forceinline__ unsigned f2h2(float a, float b) {   // lo=a, hi=b
    unsigned r;
    asm("cvt.rn.f16x2.f32 %0, %1, %2;" : "=r"(r) : "f"(b), "f"(a));
    return r;
}
__device__ __forceinline__ uint2 cvt4h(float4 v) {
    return make_uint2(f2h2(v.x, v.y), f2h2(v.z, v.w));
}
__device__ __forceinline__ void mma16(float* c, const unsigned* a, const unsigned* b) {
    asm volatile(
        "mma.sync.aligned.m16n8k16.row.col.f32.f16.f16.f32 "
        "{%0,%1,%2,%3}, {%4,%5,%6,%7}, {%8,%9}, {%0,%1,%2,%3};"
        : "+f"(c[0]), "+f"(c[1]), "+f"(c[2]), "+f"(c[3])
        : "r"(a[0]), "r"(a[1]), "r"(a[2]), "r"(a[3]), "r"(b[0]), "r"(b[1]));
}
__device__ __forceinline__ void ldsm4(unsigned* r, unsigned addr) {
    asm volatile("ldmatrix.sync.aligned.m8n8.x4.shared.b16 {%0,%1,%2,%3}, [%4];"
                 : "=r"(r[0]), "=r"(r[1]), "=r"(r[2]), "=r"(r[3]) : "r"(addr));
}

// ---------------- K0: x[N,768] @ A[768,8] -> out[N,8]  (one warp per row) -------
__global__ void lora_down_kernel(const float* __restrict__ x,
                                 const float* __restrict__ A,
                                 float* __restrict__ out) {
    int warp = (blockIdx.x * blockDim.x + threadIdx.x) >> 5;
    int lane = threadIdx.x & 31;
    if (warp >= N_) return;
    float acc[8] = {0.f,0.f,0.f,0.f,0.f,0.f,0.f,0.f};
    const float* xr = x + (size_t)warp * D_;
    for (int k = lane; k < D_; k += 32) {
        float xv = xr[k];
        float4 a0 = *(const float4*)(A + k * 8);
        float4 a1 = *(const float4*)(A + k * 8 + 4);
        acc[0] += xv * a0.x; acc[1] += xv * a0.y; acc[2] += xv * a0.z; acc[3] += xv * a0.w;
        acc[4] += xv * a1.x; acc[5] += xv * a1.y; acc[6] += xv * a1.z; acc[7] += xv * a1.w;
    }
    #pragma unroll
    for (int r = 0; r < 8; r++) {
        #pragma unroll
        for (int off = 16; off > 0; off >>= 1)
            acc[r] += __shfl_xor_sync(0xffffffffu, acc[r], off);
    }
    if (lane == 0) {
        float4* o = (float4*)(out + (size_t)warp * 8);
        o[0] = make_float4(acc[0], acc[1], acc[2], acc[3]);
        o[1] = make_float4(acc[4], acc[5], acc[6], acc[7]);
    }
}

// -------- K1: out = x + Ar[N,8] @ Bm[8,768]  -------------------------------------
__global__ void lora_up_kernel(const float* __restrict__ x,
                               const float* __restrict__ Ar,
                               const float* __restrict__ Bm,
                               float* __restrict__ out) {
    int i = blockIdx.x * blockDim.x + threadIdx.x;
    int row = i / D_;
    int col = i - row * D_;
    float4 a0 = *(const float4*)(Ar + (size_t)row * 8);
    float4 a1 = *(const float4*)(Ar + (size_t)row * 8 + 4);
    float s = x[i];
    s += a0.x * Bm[0 * D_ + col];
    s += a0.y * Bm[1 * D_ + col];
    s += a0.z * Bm[2 * D_ + col];
    s += a0.w * Bm[3 * D_ + col];
    s += a1.x * Bm[4 * D_ + col];
    s += a1.y * Bm[5 * D_ + col];
    s += a1.z * Bm[6 * D_ + col];
    s += a1.w * Bm[7 * D_ + col];
    out[i] = s;
}

// -------- K1b: pack mask ints into bits ------------------------------------------
__global__ void mask_pack_kernel(const int* __restrict__ mask,
                                 unsigned* __restrict__ mw) {
    int w = blockIdx.x * blockDim.x + threadIdx.x;
    const int4* mp = (const int4*)(mask + (size_t)w * 32);
    unsigned bits = 0;
    #pragma unroll
    for (int j = 0; j < 8; j++) {
        int4 v = mp[j];
        bits |= (v.x != 0 ? 1u : 0u) << (j * 4 + 0);
        bits |= (v.y != 0 ? 1u : 0u) << (j * 4 + 1);
        bits |= (v.z != 0 ? 1u : 0u) << (j * 4 + 2);
        bits |= (v.w != 0 ? 1u : 0u) << (j * 4 + 3);
    }
    mw[w] = bits;
}

// ---- K2: fp16 HMMA GEMM  C = scale*(A @ W^T + bias), ldmatrix frags --------------
// 256 threads = 8 warps (4m x 2n), BM=128, BN=64, BK=32, warp tile 32x32.
#define GSTW 20   // words per 32-half row (16 + 4 pad); row stride 80B
__global__ void __launch_bounds__(256)
gemm_h_kernel(const float* __restrict__ A, const float* __restrict__ W,
              const float* __restrict__ bias, float* __restrict__ C,
              float scale, int headPermute) {
    __shared__ unsigned As[2][128 * GSTW];
    __shared__ unsigned Bs[2][64 * GSTW];
    int tid = threadIdx.x;
    int warp = tid >> 5, lane = tid & 31;
    int wm = warp >> 1, wn = warp & 1;
    int lr = lane >> 2, lc = lane & 3;
    int i0 = blockIdx.x * 128, n0 = blockIdx.y * 64;

    // ldmatrix per-lane row/col adjusts
    int mIdx = lane >> 3, l7 = lane & 7;
    int rowA = ((mIdx & 1) << 3) + l7, colA = (mIdx >> 1) << 4;        // A: m1/m3 = +8 rows, m2/m3 = +16B k
    int rowB = ((mIdx >> 1) << 3) + l7, colB = (mIdx & 1) << 4;        // B: m2/m3 = +8 rows, m1/m3 = +16B k
    unsigned asB = (unsigned)__cvta_generic_to_shared(As);
    unsigned bsB = (unsigned)__cvta_generic_to_shared(Bs);

    int arow = tid >> 1, akf = (tid & 1) << 4;
    int brow = tid >> 2, bkf = (tid & 3) << 3;
    const float* Ap = A + (size_t)(i0 + arow) * D_ + akf;
    const float* Wp = W + (size_t)(n0 + brow) * D_ + bkf;
    int akw = akf >> 1, bkw = bkf >> 1;

    float c[2][4][4];
    #pragma unroll
    for (int mi = 0; mi < 2; mi++)
        #pragma unroll
        for (int ni = 0; ni < 4; ni++)
            #pragma unroll
            for (int q = 0; q < 4; q++) c[mi][ni][q] = 0.f;

    float4 ra[4], rb[2];
    #pragma unroll
    for (int p = 0; p < 4; p++) ra[p] = *(const float4*)(Ap + 4 * p);
    #pragma unroll
    for (int p = 0; p < 2; p++) rb[p] = *(const float4*)(Wp + 4 * p);
    #pragma unroll
    for (int p = 0; p < 4; p++)
        *(uint2*)&As[0][arow * GSTW + akw + 2 * p] = cvt4h(ra[p]);
    #pragma unroll
    for (int p = 0; p < 2; p++)
        *(uint2*)&Bs[0][brow * GSTW + bkw + 2 * p] = cvt4h(rb[p]);
    __syncthreads();

    for (int it = 0; it < 24; it++) {
        int buf = it & 1;
        if (it < 23) {
            int k0 = (it + 1) * 32;
            #pragma unroll
            for (int p = 0; p < 4; p++) ra[p] = *(const float4*)(Ap + k0 + 4 * p);
            #pragma unroll
            for (int p = 0; p < 2; p++) rb[p] = *(const float4*)(Wp + k0 + 4 * p);
        }

        #pragma unroll
        for (int t = 0; t < 2; t++) {   // two k16 steps; byte offset 32*t
            unsigned af[2][4], bb[2][4];
            #pragma unroll
            for (int mi = 0; mi < 2; mi++)
                ldsm4(af[mi], asB + (unsigned)((buf * 128 + wm * 32 + mi * 16 + rowA) * 80 + t * 32 + colA));
            #pragma unroll
            for (int np = 0; np < 2; np++)
                ldsm4(bb[np], bsB + (unsigned)((buf * 64 + wn * 32 + np * 16 + rowB) * 80 + t * 32 + colB));
            #pragma unroll
            for (int mi = 0; mi < 2; mi++)
                #pragma unroll
                for (int np = 0; np < 2; np++) {
                    mma16(c[mi][2 * np],     af[mi], &bb[np][0]);
                    mma16(c[mi][2 * np + 1], af[mi], &bb[np][2]);
                }
        }

        if (it < 23) {
            int nb = buf ^ 1;
            #pragma unroll
            for (int p = 0; p < 4; p++)
                *(uint2*)&As[nb][arow * GSTW + akw + 2 * p] = cvt4h(ra[p]);
            #pragma unroll
            for (int p = 0; p < 2; p++)
                *(uint2*)&Bs[nb][brow * GSTW + bkw + 2 * p] = cvt4h(rb[p]);
        }
        __syncthreads();
    }

    #pragma unroll
    for (int mi = 0; mi < 2; mi++) {
        #pragma unroll
        for (int ni = 0; ni < 4; ni++) {
            int i = i0 + wm * 32 + mi * 16 + lr;
            int j = n0 + wn * 32 + ni * 8 + 2 * lc;
            float b0 = bias[j], b1 = bias[j + 1];
            float2 o0 = make_float2(scale * (c[mi][ni][0] + b0), scale * (c[mi][ni][1] + b1));
            float2 o1 = make_float2(scale * (c[mi][ni][2] + b0), scale * (c[mi][ni][3] + b1));
            if (headPermute) {
                int bb2 = i >> 11, s = i & 2047;
                int hh = j >> 6, dk = j & 63;
                *(float2*)(C + (((size_t)(bb2 * H_ + hh)) * S_ + s) * DK_ + dk) = o0;
                *(float2*)(C + (((size_t)(bb2 * H_ + hh)) * S_ + (s + 8)) * DK_ + dk) = o1;
            } else {
                *(float2*)(C + (size_t)i * D_ + j) = o0;
                *(float2*)(C + (size_t)(i + 8) * D_ + j) = o1;
            }
        }
    }
}

// ---------------- K3: flash attention, fp16 HMMA, ldmatrix + register P ----------
// 256 threads = 8 warps, warp strip 16 q-rows, BM=128, KV tile 64.
// Q fragments register-resident; P stays in registers (S-accum == A-frag layout).
#define ASTW 36   // words per 64-half row; row stride 144B
#define ATTN_SMEM ((64 * ASTW + 64 * ASTW) * 4)
__global__ void __launch_bounds__(256, 2)
attn_h_kernel(const unsigned* __restrict__ mw, float* __restrict__ out) {
    extern __shared__ unsigned sm[];
    unsigned* Ks = sm;                    // [64][ASTW]  kv rows, dk halves contiguous
    unsigned* Vt = Ks + 64 * ASTW;        // [64][ASTW]  dk rows, kv-pair halves

    int tid = threadIdx.x, warp = tid >> 5, lane = tid & 31;
    int lr = lane >> 2, lc = lane & 3;
    int rb = warp * 16;
    int qb = blockIdx.x, h = blockIdx.y, b = blockIdx.z;
    int q0 = qb * 128, bh = b * H_ + h;

    const float* qg = g_qh + ((size_t)bh * S_ + q0) * DK_;
    const float* kg = g_kh + (size_t)bh * S_ * DK_;
    const float* vg = g_vh + (size_t)bh * S_ * DK_;

    // ldmatrix B-pattern adjusts (rows = n, contiguous = k)
    int mIdx = lane >> 3, l7 = lane & 7;
    int rowB = ((mIdx >> 1) << 3) + l7, colB = (mIdx & 1) << 4;
    unsigned ksB = (unsigned)__cvta_generic_to_shared(Ks);
    unsigned vtB = (unsigned)__cvta_generic_to_shared(Vt);

    int lrow = tid >> 4, lcf = (tid & 15) << 2;
    int lcw = lcf >> 1;

    // Q fragments from gmem (q pre-scaled by 1/8): qf[t] = A-frag for k16 step t
    unsigned qf[4][4];
    {
        const float* q0p = qg + (size_t)(rb + lr) * DK_;
        const float* q1p = qg + (size_t)(rb + lr + 8) * DK_;
        #pragma unroll
        for (int t = 0; t < 4; t++) {
            float2 x;
            x = *(const float2*)(q0p + 16 * t + 2 * lc);     qf[t][0] = f2h2(x.x, x.y);
            x = *(const float2*)(q1p + 16 * t + 2 * lc);     qf[t][1] = f2h2(x.x, x.y);
            x = *(const float2*)(q0p + 16 * t + 8 + 2 * lc); qf[t][2] = f2h2(x.x, x.y);
            x = *(const float2*)(q1p + 16 * t + 8 + 2 * lc); qf[t][3] = f2h2(x.x, x.y);
        }
    }

    float o[8][4];
    float m[2], l[2];
    m[0] = -1e30f; m[1] = -1e30f; l[0] = 0.f; l[1] = 0.f;
    #pragma unroll
    for (int ni = 0; ni < 8; ni++)
        #pragma unroll
        for (int q = 0; q < 4; q++) o[ni][q] = 0.f;

    for (int kb = 0; kb < S_ / 64; kb++) {
        int k0 = kb * 64;
        __syncthreads();
        // K rows (dk contiguous)
        #pragma unroll
        for (int p = 0; p < 4; p++) {
            int row = lrow + p * 16;
            *(uint2*)&Ks[row * ASTW + lcw] =
                cvt4h(*(const float4*)(kg + (size_t)(k0 + row) * DK_ + lcf));
        }
        // V transposed pair-packed: Vt[dk][r2] = half2(V[2r2][dk], V[2r2+1][dk])
        #pragma unroll
        for (int p = 0; p < 2; p++) {
            int t = tid + p * 256;
            int r2 = t & 31, dk4 = (t >> 5) << 2;
            float4 va = *(const float4*)(vg + (size_t)(k0 + 2 * r2) * DK_ + dk4);
            float4 vb = *(const float4*)(vg + (size_t)(k0 + 2 * r2 + 1) * DK_ + dk4);
            Vt[(dk4 + 0) * ASTW + r2] = f2h2(va.x, vb.x);
            Vt[(dk4 + 1) * ASTW + r2] = f2h2(va.y, vb.y);
            Vt[(dk4 + 2) * ASTW + r2] = f2h2(va.z, vb.z);
            Vt[(dk4 + 3) * ASTW + r2] = f2h2(va.w, vb.w);
        }
        __syncthreads();

        // --- S = Q K^T ---
        float s[8][4];
        #pragma unroll
        for (int ni = 0; ni < 8; ni++)
            #pragma unroll
            for (int q = 0; q < 4; q++) s[ni][q] = 0.f;

        #pragma unroll
        for (int t = 0; t < 4; t++) {          // k16 steps; byte offset 32*t
            #pragma unroll
            for (int np = 0; np < 4; np++) {   // kv-tile pairs
                unsigned bf[4];
                ldsm4(bf, ksB + (unsigned)((np * 16 + rowB) * 144 + t * 32 + colB));
                mma16(s[2 * np],     qf[t], &bf[0]);
                mma16(s[2 * np + 1], qf[t], &bf[2]);
            }
        }

        // --- mask + online softmax (all in registers; overwrite s with p) ---
        #pragma unroll
        for (int hh = 0; hh < 2; hh++) {
            int grow = q0 + rb + hh * 8 + lr;
            uint2 w = *(const uint2*)(mw + ((size_t)b * S_ + grow) * (S_ / 32) + kb * 2);
            float rmax = -1e30f;
            #pragma unroll
            for (int ni = 0; ni < 8; ni++) {
                int col = ni * 8 + 2 * lc;
                unsigned ws = (col < 32) ? w.x : w.y;
                int bit = col & 31;
                float* sp = &s[ni][hh * 2];
                if (!((ws >> bit) & 1u))       sp[0] = -1e9f;
                if (!((ws >> (bit + 1)) & 1u)) sp[1] = -1e9f;
                rmax = fmaxf(rmax, fmaxf(sp[0], sp[1]));
            }
            rmax = fmaxf(rmax, __shfl_xor_sync(0xffffffffu, rmax, 1));
            rmax = fmaxf(rmax, __shfl_xor_sync(0xffffffffu, rmax, 2));
            float mn = fmaxf(m[hh], rmax);
            float corr = __expf(m[hh] - mn);
            m[hh] = mn;
            float rs = 0.f;
            #pragma unroll
            for (int ni = 0; ni < 8; ni++) {
                float* sp = &s[ni][hh * 2];
                float p0 = __expf(sp[0] - mn);
                float p1 = __expf(sp[1] - mn);
                rs += p0 + p1;
                sp[0] = p0; sp[1] = p1;
                o[ni][hh * 2]     *= corr;
                o[ni][hh * 2 + 1] *= corr;
            }
            rs += __shfl_xor_sync(0xffffffffu, rs, 1);
            rs += __shfl_xor_sync(0xffffffffu, rs, 2);
            l[hh] = l[hh] * corr + rs;
        }

        // --- O += P @ V  (A-frags packed from s registers) ---
        #pragma unroll
        for (int t = 0; t < 4; t++) {          // kv k16 step = s-tiles 2t, 2t+1
            unsigned a[4];
            a[0] = f2h2(s[2 * t][0],     s[2 * t][1]);
            a[1] = f2h2(s[2 * t][2],     s[2 * t][3]);
            a[2] = f2h2(s[2 * t + 1][0], s[2 * t + 1][1]);
            a[3] = f2h2(s[2 * t + 1][2], s[2 * t + 1][3]);
            #pragma unroll
            for (int np = 0; np < 4; np++) {   // dk-tile pairs
                unsigned bf[4];
                ldsm4(bf, vtB + (unsigned)((np * 16 + rowB) * 144 + t * 32 + colB));
                mma16(o[2 * np],     a, &bf[0]);
                mma16(o[2 * np + 1], a, &bf[2]);
            }
        }
    }

    // --- epilogue: O / l -> out [B,S,D] ---
    #pragma unroll
    for (int hh = 0; hh < 2; hh++) {
        float inv = 1.0f / l[hh];
        int grow = q0 + rb + hh * 8 + lr;
        #pragma unroll
        for (int ni = 0; ni < 8; ni++) {
            int col = ni * 8 + 2 * lc;
            float2 ov = make_float2(o[ni][hh * 2] * inv, o[ni][hh * 2 + 1] * inv);
            *(float2*)(out + ((size_t)(b * S_ + grow)) * D_ + h * DK_ + col) = ov;
        }
    }
}

// --------------------------------- host ------------------------------------------
extern "C" void kernel_launch(void* const* d_in, const int* in_sizes, int n_in,
                              void* d_out, int out_size) {
    const float* query = (const float*)d_in[0];
    const float* key   = (const float*)d_in[1];
    const float* value = (const float*)d_in[2];
    const int*   mask  = (const int*)d_in[3];
    const float* lAq   = (const float*)d_in[4];
    const float* lBq   = (const float*)d_in[5];
    const float* lAv   = (const float*)d_in[6];
    const float* lBv   = (const float*)d_in[7];
    const float* Wq    = (const float*)d_in[8];
    const float* bq    = (const float*)d_in[9];
    const float* Wk    = (const float*)d_in[10];
    const float* bk    = (const float*)d_in[11];
    const float* Wv    = (const float*)d_in[12];
    const float* bv    = (const float*)d_in[13];
    const float* Wm    = (const float*)d_in[14];
    const float* bm    = (const float*)d_in[15];
    float* out = (float*)d_out;

    void *pAq, *pAv, *pQadj, *pVadj, *pqh, *pkh, *pvh, *pao, *pmw;
    cudaGetSymbolAddress(&pAq,   g_Aq);
    cudaGetSymbolAddress(&pAv,   g_Av);
    cudaGetSymbolAddress(&pQadj, g_Qadj);
    cudaGetSymbolAddress(&pVadj, g_Vadj);
    cudaGetSymbolAddress(&pqh,   g_qh);
    cudaGetSymbolAddress(&pkh,   g_kh);
    cudaGetSymbolAddress(&pvh,   g_vh);
    cudaGetSymbolAddress(&pao,   g_ao);
    cudaGetSymbolAddress(&pmw,   g_mw);

    // mask pack (independent, kick off first)
    mask_pack_kernel<<<(B_ * S_ * (S_ / 32)) / 256, 256>>>(mask, (unsigned*)pmw);

    // LoRA down
    lora_down_kernel<<<N_ / 8, 256>>>(query, lAq, (float*)pAq);
    lora_down_kernel<<<N_ / 8, 256>>>(value, lAv, (float*)pAv);

    // LoRA up + residual
    lora_up_kernel<<<(N_ * D_) / 256, 256>>>(query, (const float*)pAq, lBq, (float*)pQadj);
    lora_up_kernel<<<(N_ * D_) / 256, 256>>>(value, (const float*)pAv, lBv, (float*)pVadj);

    // Projections (reference's stream swap preserved)
    dim3 gg(N_ / 128, D_ / 64);
    gemm_h_kernel<<<gg, 256>>>((const float*)pQadj, Wv, bv, (float*)pvh, 1.0f,   1);
    gemm_h_kernel<<<gg, 256>>>(key,                 Wk, bk, (float*)pkh, 1.0f,   1);
    gemm_h_kernel<<<gg, 256>>>((const float*)pVadj, Wq, bq, (float*)pqh, 0.125f, 1);

    // Flash attention (fp16 tensor cores) -> g_ao [B,S,D]
    cudaFuncSetAttribute(attn_h_kernel, cudaFuncAttributeMaxDynamicSharedMemorySize, ATTN_SMEM);
    attn_h_kernel<<<dim3(S_ / 128, H_, B_), 256, ATTN_SMEM>>>((const unsigned*)pmw, (float*)pao);

    // Final: out = g_ao @ Wm^T + bm
    gemm_h_kernel<<<gg, 256>>>((const float*)pao, Wm, bm, out, 1.0f, 0);
}

// round 8
// speedup vs baseline: 1.5387x; 1.1433x over previous
#include <cuda_runtime.h>
#include <cuda_fp16.h>
#include <cstdint>

#define B_ 2
#define S_ 2048
#define D_ 768
#define H_ 12
#define DK_ 64
#define R_ 8
#define N_ 4096   // B_*S_

// ---------------- scratch (static device globals; no allocation) ----------------
__device__ float g_Aq[N_ * R_];
__device__ float g_Av[N_ * R_];
__device__ float g_Qadj[(size_t)N_ * D_];
__device__ float g_Vadj[(size_t)N_ * D_];
__device__ __half g_qh[(size_t)N_ * D_];  // [B,H,S,DK] fp16, pre-scaled by 1/8
__device__ __half g_kh[(size_t)N_ * D_];  // [B,H,S,DK] fp16
__device__ __half g_vh[(size_t)N_ * D_];  // [B,H,S,DK] fp16
__device__ float g_ao[(size_t)N_ * D_];   // [B,S,D] attention output (fp32)
__device__ unsigned g_mw[B_ * S_ * (S_ / 32)];  // packed mask bits

// ---------------- fp16 / mma / ldmatrix / cp.async helpers -----------------------
__device__ __forceinline__ unsigned f2h2(float a, float b) {   // lo=a, hi=b
    unsigned r;
    asm("cvt.rn.f16x2.f32 %0, %1, %2;" : "=r"(r) : "f"(b), "f"(a));
    return r;
}
__device__ __forceinline__ uint2 cvt4h(float4 v) {
    return make_uint2(f2h2(v.x, v.y), f2h2(v.z, v.w));
}
__device__ __forceinline__ void mma16(float* c, const unsigned* a, const unsigned* b) {
    asm volatile(
        "mma.sync.aligned.m16n8k16.row.col.f32.f16.f16.f32 "
        "{%0,%1,%2,%3}, {%4,%5,%6,%7}, {%8,%9}, {%0,%1,%2,%3};"
        : "+f"(c[0]), "+f"(c[1]), "+f"(c[2]), "+f"(c[3])
        : "r"(a[0]), "r"(a[1]), "r"(a[2]), "r"(a[3]), "r"(b[0]), "r"(b[1]));
}
__device__ __forceinline__ void ldsm4(unsigned* r, unsigned addr) {
    asm volatile("ldmatrix.sync.aligned.m8n8.x4.shared.b16 {%0,%1,%2,%3}, [%4];"
                 : "=r"(r[0]), "=r"(r[1]), "=r"(r[2]), "=r"(r[3]) : "r"(addr));
}
__device__ __forceinline__ void ldsm4t(unsigned* r, unsigned addr) {
    asm volatile("ldmatrix.sync.aligned.m8n8.x4.trans.shared.b16 {%0,%1,%2,%3}, [%4];"
                 : "=r"(r[0]), "=r"(r[1]), "=r"(r[2]), "=r"(r[3]) : "r"(addr));
}
__device__ __forceinline__ void cp16(unsigned dst, const void* src) {
    asm volatile("cp.async.cg.shared.global [%0], [%1], 16;" :: "r"(dst), "l"(src));
}
__device__ __forceinline__ void cp_commit() { asm volatile("cp.async.commit_group;"); }
template <int NN>
__device__ __forceinline__ void cp_wait() {
    asm volatile("cp.async.wait_group %0;" :: "n"(NN));
}

// ---------------- K0: x[N,768] @ A[768,8] -> out[N,8]  (one warp per row) -------
__global__ void lora_down_kernel(const float* __restrict__ x,
                                 const float* __restrict__ A,
                                 float* __restrict__ out) {
    int warp = (blockIdx.x * blockDim.x + threadIdx.x) >> 5;
    int lane = threadIdx.x & 31;
    if (warp >= N_) return;
    float acc[8] = {0.f,0.f,0.f,0.f,0.f,0.f,0.f,0.f};
    const float* xr = x + (size_t)warp * D_;
    for (int k = lane; k < D_; k += 32) {
        float xv = xr[k];
        float4 a0 = *(const float4*)(A + k * 8);
        float4 a1 = *(const float4*)(A + k * 8 + 4);
        acc[0] += xv * a0.x; acc[1] += xv * a0.y; acc[2] += xv * a0.z; acc[3] += xv * a0.w;
        acc[4] += xv * a1.x; acc[5] += xv * a1.y; acc[6] += xv * a1.z; acc[7] += xv * a1.w;
    }
    #pragma unroll
    for (int r = 0; r < 8; r++) {
        #pragma unroll
        for (int off = 16; off > 0; off >>= 1)
            acc[r] += __shfl_xor_sync(0xffffffffu, acc[r], off);
    }
    if (lane == 0) {
        float4* o = (float4*)(out + (size_t)warp * 8);
        o[0] = make_float4(acc[0], acc[1], acc[2], acc[3]);
        o[1] = make_float4(acc[4], acc[5], acc[6], acc[7]);
    }
}

// -------- K1: out = x + Ar[N,8] @ Bm[8,768]  -------------------------------------
__global__ void lora_up_kernel(const float* __restrict__ x,
                               const float* __restrict__ Ar,
                               const float* __restrict__ Bm,
                               float* __restrict__ out) {
    int i = blockIdx.x * blockDim.x + threadIdx.x;
    int row = i / D_;
    int col = i - row * D_;
    float4 a0 = *(const float4*)(Ar + (size_t)row * 8);
    float4 a1 = *(const float4*)(Ar + (size_t)row * 8 + 4);
    float s = x[i];
    s += a0.x * Bm[0 * D_ + col];
    s += a0.y * Bm[1 * D_ + col];
    s += a0.z * Bm[2 * D_ + col];
    s += a0.w * Bm[3 * D_ + col];
    s += a1.x * Bm[4 * D_ + col];
    s += a1.y * Bm[5 * D_ + col];
    s += a1.z * Bm[6 * D_ + col];
    s += a1.w * Bm[7 * D_ + col];
    out[i] = s;
}

// -------- K1b: pack mask ints into bits ------------------------------------------
__global__ void mask_pack_kernel(const int* __restrict__ mask,
                                 unsigned* __restrict__ mw) {
    int w = blockIdx.x * blockDim.x + threadIdx.x;
    const int4* mp = (const int4*)(mask + (size_t)w * 32);
    unsigned bits = 0;
    #pragma unroll
    for (int j = 0; j < 8; j++) {
        int4 v = mp[j];
        bits |= (v.x != 0 ? 1u : 0u) << (j * 4 + 0);
        bits |= (v.y != 0 ? 1u : 0u) << (j * 4 + 1);
        bits |= (v.z != 0 ? 1u : 0u) << (j * 4 + 2);
        bits |= (v.w != 0 ? 1u : 0u) << (j * 4 + 3);
    }
    mw[w] = bits;
}

// ---- K2: fp16 HMMA GEMM, ldmatrix frags; C fp32 or head-permuted fp16 -----------
// 256 threads = 8 warps (4m x 2n), BM=128, BN=64, BK=32, warp tile 32x32.
#define GSTW 20   // words per 32-half row (16 + 4 pad); row stride 80B
__global__ void __launch_bounds__(256)
gemm_h_kernel(const float* __restrict__ A, const float* __restrict__ W,
              const float* __restrict__ bias, void* __restrict__ Cv,
              float scale, int headPermute) {
    __shared__ unsigned As[2][128 * GSTW];
    __shared__ unsigned Bs[2][64 * GSTW];
    int tid = threadIdx.x;
    int warp = tid >> 5, lane = tid & 31;
    int wm = warp >> 1, wn = warp & 1;
    int lr = lane >> 2, lc = lane & 3;
    int i0 = blockIdx.x * 128, n0 = blockIdx.y * 64;

    int mIdx = lane >> 3, l7 = lane & 7;
    int rowA = ((mIdx & 1) << 3) + l7, colA = (mIdx >> 1) << 4;
    int rowB = ((mIdx >> 1) << 3) + l7, colB = (mIdx & 1) << 4;
    unsigned asB = (unsigned)__cvta_generic_to_shared(As);
    unsigned bsB = (unsigned)__cvta_generic_to_shared(Bs);

    int arow = tid >> 1, akf = (tid & 1) << 4;
    int brow = tid >> 2, bkf = (tid & 3) << 3;
    const float* Ap = A + (size_t)(i0 + arow) * D_ + akf;
    const float* Wp = W + (size_t)(n0 + brow) * D_ + bkf;
    int akw = akf >> 1, bkw = bkf >> 1;

    float c[2][4][4];
    #pragma unroll
    for (int mi = 0; mi < 2; mi++)
        #pragma unroll
        for (int ni = 0; ni < 4; ni++)
            #pragma unroll
            for (int q = 0; q < 4; q++) c[mi][ni][q] = 0.f;

    float4 ra[4], rb[2];
    #pragma unroll
    for (int p = 0; p < 4; p++) ra[p] = *(const float4*)(Ap + 4 * p);
    #pragma unroll
    for (int p = 0; p < 2; p++) rb[p] = *(const float4*)(Wp + 4 * p);
    #pragma unroll
    for (int p = 0; p < 4; p++)
        *(uint2*)&As[0][arow * GSTW + akw + 2 * p] = cvt4h(ra[p]);
    #pragma unroll
    for (int p = 0; p < 2; p++)
        *(uint2*)&Bs[0][brow * GSTW + bkw + 2 * p] = cvt4h(rb[p]);
    __syncthreads();

    for (int it = 0; it < 24; it++) {
        int buf = it & 1;
        if (it < 23) {
            int k0 = (it + 1) * 32;
            #pragma unroll
            for (int p = 0; p < 4; p++) ra[p] = *(const float4*)(Ap + k0 + 4 * p);
            #pragma unroll
            for (int p = 0; p < 2; p++) rb[p] = *(const float4*)(Wp + k0 + 4 * p);
        }

        #pragma unroll
        for (int t = 0; t < 2; t++) {
            unsigned af[2][4], bb[2][4];
            #pragma unroll
            for (int mi = 0; mi < 2; mi++)
                ldsm4(af[mi], asB + (unsigned)((buf * 128 + wm * 32 + mi * 16 + rowA) * 80 + t * 32 + colA));
            #pragma unroll
            for (int np = 0; np < 2; np++)
                ldsm4(bb[np], bsB + (unsigned)((buf * 64 + wn * 32 + np * 16 + rowB) * 80 + t * 32 + colB));
            #pragma unroll
            for (int mi = 0; mi < 2; mi++)
                #pragma unroll
                for (int np = 0; np < 2; np++) {
                    mma16(c[mi][2 * np],     af[mi], &bb[np][0]);
                    mma16(c[mi][2 * np + 1], af[mi], &bb[np][2]);
                }
        }

        if (it < 23) {
            int nb = buf ^ 1;
            #pragma unroll
            for (int p = 0; p < 4; p++)
                *(uint2*)&As[nb][arow * GSTW + akw + 2 * p] = cvt4h(ra[p]);
            #pragma unroll
            for (int p = 0; p < 2; p++)
                *(uint2*)&Bs[nb][brow * GSTW + bkw + 2 * p] = cvt4h(rb[p]);
        }
        __syncthreads();
    }

    #pragma unroll
    for (int mi = 0; mi < 2; mi++) {
        #pragma unroll
        for (int ni = 0; ni < 4; ni++) {
            int i = i0 + wm * 32 + mi * 16 + lr;
            int j = n0 + wn * 32 + ni * 8 + 2 * lc;
            float b0 = bias[j], b1 = bias[j + 1];
            float v00 = scale * (c[mi][ni][0] + b0), v01 = scale * (c[mi][ni][1] + b1);
            float v10 = scale * (c[mi][ni][2] + b0), v11 = scale * (c[mi][ni][3] + b1);
            if (headPermute) {
                __half* Ch = (__half*)Cv;
                int bb2 = i >> 11, s = i & 2047;
                int hh = j >> 6, dk = j & 63;
                *(unsigned*)(Ch + (((size_t)(bb2 * H_ + hh)) * S_ + s) * DK_ + dk) = f2h2(v00, v01);
                *(unsigned*)(Ch + (((size_t)(bb2 * H_ + hh)) * S_ + (s + 8)) * DK_ + dk) = f2h2(v10, v11);
            } else {
                float* Cf = (float*)Cv;
                *(float2*)(Cf + (size_t)i * D_ + j) = make_float2(v00, v01);
                *(float2*)(Cf + (size_t)(i + 8) * D_ + j) = make_float2(v10, v11);
            }
        }
    }
}

// ---------------- K3: flash attention — fp16 inputs, cp.async, ldmatrix ----------
// 256 threads = 8 warps, warp strip 16 q-rows, BM=128, KV tile 64.
// K and V both stored row-major [kv][dk] fp16 in smem; V frags via ldmatrix.trans.
#define ASTW 36   // words per 64-half row; row stride 144B (conflict-free ldsm)
#define ATTN_SMEM (4 * 64 * ASTW * 4)   // K[2] + V[2]
__global__ void __launch_bounds__(256, 2)
attn_h_kernel(const unsigned* __restrict__ mw, float* __restrict__ out) {
    extern __shared__ unsigned sm[];
    unsigned* Ks = sm;                    // [2][64][ASTW]
    unsigned* Vs = sm + 2 * 64 * ASTW;    // [2][64][ASTW]

    int tid = threadIdx.x, warp = tid >> 5, lane = tid & 31;
    int lr = lane >> 2, lc = lane & 3;
    int rb = warp * 16;
    int qb = blockIdx.x, h = blockIdx.y, b = blockIdx.z;
    int q0 = qb * 128, bh = b * H_ + h;

    const __half* qg = g_qh + ((size_t)bh * S_ + q0) * DK_;
    const __half* kg = g_kh + (size_t)bh * S_ * DK_;
    const __half* vg = g_vh + (size_t)bh * S_ * DK_;

    int mIdx = lane >> 3, l7 = lane & 7;
    int rowK = ((mIdx >> 1) << 3) + l7, colK = (mIdx & 1) << 4;   // K non-trans B
    int rowV = ((mIdx & 1) << 3) + l7, colV = (mIdx >> 1) << 4;   // V trans B
    unsigned ksB = (unsigned)__cvta_generic_to_shared(Ks);
    unsigned vsB = (unsigned)__cvta_generic_to_shared(Vs);

    // cp.async fill mapping: 512 16B-chunks per tensor per tile, 2 per thread
    int r0c = tid >> 3, c0c = (tid & 7) << 3;          // chunk 0: row, half-offset
    int r1c = (tid + 256) >> 3, c1c = c0c;             // chunk 1 (rows 32..63)

    // Q fragments straight from gmem (half2 words)
    unsigned qf[4][4];
    {
        const unsigned* u0 = (const unsigned*)(qg + (size_t)(rb + lr) * DK_);
        const unsigned* u1 = (const unsigned*)(qg + (size_t)(rb + lr + 8) * DK_);
        #pragma unroll
        for (int t = 0; t < 4; t++) {
            qf[t][0] = u0[8 * t + lc];
            qf[t][1] = u1[8 * t + lc];
            qf[t][2] = u0[8 * t + 4 + lc];
            qf[t][3] = u1[8 * t + 4 + lc];
        }
    }

    // prologue: issue tile 0
    {
        cp16(ksB + (unsigned)(r0c * 144 + c0c * 2), kg + (size_t)r0c * DK_ + c0c);
        cp16(ksB + (unsigned)(r1c * 144 + c1c * 2), kg + (size_t)r1c * DK_ + c1c);
        cp16(vsB + (unsigned)(r0c * 144 + c0c * 2), vg + (size_t)r0c * DK_ + c0c);
        cp16(vsB + (unsigned)(r1c * 144 + c1c * 2), vg + (size_t)r1c * DK_ + c1c);
        cp_commit();
    }

    float o[8][4];
    float m[2], l[2];
    m[0] = -1e30f; m[1] = -1e30f; l[0] = 0.f; l[1] = 0.f;
    #pragma unroll
    for (int ni = 0; ni < 8; ni++)
        #pragma unroll
        for (int q = 0; q < 4; q++) o[ni][q] = 0.f;

    for (int kb = 0; kb < S_ / 64; kb++) {
        int buf = kb & 1;
        if (kb + 1 < S_ / 64) {
            int nb = buf ^ 1;
            size_t k0n = (size_t)(kb + 1) * 64;
            cp16(ksB + (unsigned)((nb * 64 + r0c) * 144 + c0c * 2), kg + (k0n + r0c) * DK_ + c0c);
            cp16(ksB + (unsigned)((nb * 64 + r1c) * 144 + c1c * 2), kg + (k0n + r1c) * DK_ + c1c);
            cp16(vsB + (unsigned)((nb * 64 + r0c) * 144 + c0c * 2), vg + (k0n + r0c) * DK_ + c0c);
            cp16(vsB + (unsigned)((nb * 64 + r1c) * 144 + c1c * 2), vg + (k0n + r1c) * DK_ + c1c);
            cp_commit();
            cp_wait<1>();
        } else {
            cp_wait<0>();
        }
        __syncthreads();

        unsigned kbase = ksB + (unsigned)(buf * 64) * 144;
        unsigned vbase = vsB + (unsigned)(buf * 64) * 144;

        // --- S = Q K^T ---
        float s[8][4];
        #pragma unroll
        for (int ni = 0; ni < 8; ni++)
            #pragma unroll
            for (int q = 0; q < 4; q++) s[ni][q] = 0.f;

        #pragma unroll
        for (int t = 0; t < 4; t++) {
            #pragma unroll
            for (int np = 0; np < 4; np++) {
                unsigned bf[4];
                ldsm4(bf, kbase + (unsigned)((np * 16 + rowK) * 144 + t * 32 + colK));
                mma16(s[2 * np],     qf[t], &bf[0]);
                mma16(s[2 * np + 1], qf[t], &bf[2]);
            }
        }

        // --- mask + online softmax (registers only) ---
        #pragma unroll
        for (int hh = 0; hh < 2; hh++) {
            int grow = q0 + rb + hh * 8 + lr;
            uint2 w = *(const uint2*)(mw + ((size_t)b * S_ + grow) * (S_ / 32) + kb * 2);
            float rmax = -1e30f;
            #pragma unroll
            for (int ni = 0; ni < 8; ni++) {
                int col = ni * 8 + 2 * lc;
                unsigned ws = (col < 32) ? w.x : w.y;
                int bit = col & 31;
                float* sp = &s[ni][hh * 2];
                if (!((ws >> bit) & 1u))       sp[0] = -1e9f;
                if (!((ws >> (bit + 1)) & 1u)) sp[1] = -1e9f;
                rmax = fmaxf(rmax, fmaxf(sp[0], sp[1]));
            }
            rmax = fmaxf(rmax, __shfl_xor_sync(0xffffffffu, rmax, 1));
            rmax = fmaxf(rmax, __shfl_xor_sync(0xffffffffu, rmax, 2));
            float mn = fmaxf(m[hh], rmax);
            float corr = __expf(m[hh] - mn);
            m[hh] = mn;
            float rs = 0.f;
            #pragma unroll
            for (int ni = 0; ni < 8; ni++) {
                float* sp = &s[ni][hh * 2];
                float p0 = __expf(sp[0] - mn);
                float p1 = __expf(sp[1] - mn);
                rs += p0 + p1;
                sp[0] = p0; sp[1] = p1;
                o[ni][hh * 2]     *= corr;
                o[ni][hh * 2 + 1] *= corr;
            }
            rs += __shfl_xor_sync(0xffffffffu, rs, 1);
            rs += __shfl_xor_sync(0xffffffffu, rs, 2);
            l[hh] = l[hh] * corr + rs;
        }

        // --- O += P @ V  (A-frags from registers; B-frags via trans ldmatrix) ---
        #pragma unroll
        for (int t = 0; t < 4; t++) {
            unsigned a[4];
            a[0] = f2h2(s[2 * t][0],     s[2 * t][1]);
            a[1] = f2h2(s[2 * t][2],     s[2 * t][3]);
            a[2] = f2h2(s[2 * t + 1][0], s[2 * t + 1][1]);
            a[3] = f2h2(s[2 * t + 1][2], s[2 * t + 1][3]);
            #pragma unroll
            for (int np = 0; np < 4; np++) {
                unsigned bf[4];
                ldsm4t(bf, vbase + (unsigned)((t * 16 + rowV) * 144 + np * 32 + colV));
                mma16(o[2 * np],     a, &bf[0]);
                mma16(o[2 * np + 1], a, &bf[2]);
            }
        }
        __syncthreads();   // all reads of this buffer done before next overwrite
    }

    // --- epilogue: O / l -> out [B,S,D] fp32 ---
    #pragma unroll
    for (int hh = 0; hh < 2; hh++) {
        float inv = 1.0f / l[hh];
        int grow = q0 + rb + hh * 8 + lr;
        #pragma unroll
        for (int ni = 0; ni < 8; ni++) {
            int col = ni * 8 + 2 * lc;
            float2 ov = make_float2(o[ni][hh * 2] * inv, o[ni][hh * 2 + 1] * inv);
            *(float2*)(out + ((size_t)(b * S_ + grow)) * D_ + h * DK_ + col) = ov;
        }
    }
}

// --------------------------------- host ------------------------------------------
extern "C" void kernel_launch(void* const* d_in, const int* in_sizes, int n_in,
                              void* d_out, int out_size) {
    const float* query = (const float*)d_in[0];
    const float* key   = (const float*)d_in[1];
    const float* value = (const float*)d_in[2];
    const int*   mask  = (const int*)d_in[3];
    const float* lAq   = (const float*)d_in[4];
    const float* lBq   = (const float*)d_in[5];
    const float* lAv   = (const float*)d_in[6];
    const float* lBv   = (const float*)d_in[7];
    const float* Wq    = (const float*)d_in[8];
    const float* bq    = (const float*)d_in[9];
    const float* Wk    = (const float*)d_in[10];
    const float* bk    = (const float*)d_in[11];
    const float* Wv    = (const float*)d_in[12];
    const float* bv    = (const float*)d_in[13];
    const float* Wm    = (const float*)d_in[14];
    const float* bm    = (const float*)d_in[15];
    float* out = (float*)d_out;

    void *pAq, *pAv, *pQadj, *pVadj, *pqh, *pkh, *pvh, *pao, *pmw;
    cudaGetSymbolAddress(&pAq,   g_Aq);
    cudaGetSymbolAddress(&pAv,   g_Av);
    cudaGetSymbolAddress(&pQadj, g_Qadj);
    cudaGetSymbolAddress(&pVadj, g_Vadj);
    cudaGetSymbolAddress(&pqh,   g_qh);
    cudaGetSymbolAddress(&pkh,   g_kh);
    cudaGetSymbolAddress(&pvh,   g_vh);
    cudaGetSymbolAddress(&pao,   g_ao);
    cudaGetSymbolAddress(&pmw,   g_mw);

    // mask pack (independent, kick off first)
    mask_pack_kernel<<<(B_ * S_ * (S_ / 32)) / 256, 256>>>(mask, (unsigned*)pmw);

    // LoRA down
    lora_down_kernel<<<N_ / 8, 256>>>(query, lAq, (float*)pAq);
    lora_down_kernel<<<N_ / 8, 256>>>(value, lAv, (float*)pAv);

    // LoRA up + residual
    lora_up_kernel<<<(N_ * D_) / 256, 256>>>(query, (const float*)pAq, lBq, (float*)pQadj);
    lora_up_kernel<<<(N_ * D_) / 256, 256>>>(value, (const float*)pAv, lBv, (float*)pVadj);

    // Projections (reference's stream swap preserved), outputs fp16 head-major
    dim3 gg(N_ / 128, D_ / 64);
    gemm_h_kernel<<<gg, 256>>>((const float*)pQadj, Wv, bv, pvh, 1.0f,   1);
    gemm_h_kernel<<<gg, 256>>>(key,                 Wk, bk, pkh, 1.0f,   1);
    gemm_h_kernel<<<gg, 256>>>((const float*)pVadj, Wq, bq, pqh, 0.125f, 1);

    // Flash attention (fp16 tensor cores) -> g_ao [B,S,D] fp32
    cudaFuncSetAttribute(attn_h_kernel, cudaFuncAttributeMaxDynamicSharedMemorySize, ATTN_SMEM);
    attn_h_kernel<<<dim3(S_ / 128, H_, B_), 256, ATTN_SMEM>>>((const unsigned*)pmw, (float*)pao);

    // Final: out = g_ao @ Wm^T + bm (fp32 out)
    gemm_h_kernel<<<gg, 256>>>((const float*)pao, Wm, bm, d_out, 1.0f, 0);
}